// round 13
// baseline (speedup 1.0000x reference)
#include <cuda_runtime.h>
#include <cstddef>
#include <cstdint>

#define N_NODES 50000
#define N_EDGES 800000
#define N_GRAPHS 50
#define NODES_PER_GRAPH 1000

#define CAP_L2 32768      // edges into flag2 nodes (expected ~13.4K)
#define CAP_L3 4096       // master-destination edges (expected ~800)
#define CAP_N1 24576      // nodes needing x1 (expected ~14.2K)
#define CAP_N2 4096       // nodes needing x2 (expected ~850)

#define POS_GATHER ((const int*)(size_t)1)   // sentinel: use list position as row

#define SCAN_B 256
#define SCAN_NB ((N_NODES + SCAN_B - 1) / SCAN_B)   // 196

// Scratch (device globals; allocation rules forbid cudaMalloc)
__device__ float g_x1[(size_t)N_NODES * 128];
__device__ float g_x2[(size_t)N_NODES * 128];
__device__ float g_aggx[(size_t)N_NODES * 256];    // sum x[src] per dst (layer 1)
__device__ float g_agga[(size_t)N_NODES * 128];    // sum edge_attr per dst (layer 1)
__device__ float g_aggx2[(size_t)N_NODES * 128];   // sum relu_x1[src] per dst (layer 2)
__device__ float g_agge1[(size_t)N_NODES * 64];    // sum e1 per dst (layer 2)
__device__ float g_ec[(size_t)CAP_L2 * 64];        // e0 rows, list2-position indexed
__device__ float g_e1c[(size_t)CAP_L2 * 64];       // e1 rows, list2-position indexed
__device__ float g_e2c[(size_t)CAP_L3 * 64];       // e2 rows, list3-position indexed
__device__ float g_wpm[128 * 128];                 // w_proj @ wme1
__device__ float g_bpm[128];                       // b_proj @ wme1

__device__ int d_flag1[N_NODES];
__device__ int d_flag2[N_NODES];
__device__ int d_deg[N_NODES];     // FULL in-degree of every node
__device__ int d_off[N_NODES];     // CSR exclusive offsets
__device__ int d_cur[N_NODES];     // scatter cursors
__device__ int d_csr[N_EDGES];     // edge ids grouped by dst
__device__ int d_bsum[SCAN_NB];    // per-block sums for scan
__device__ int d_list2[CAP_L2];
__device__ int d_list3[CAP_L3];
__device__ int d_pos2[N_EDGES];    // edge id -> list2 position (valid for list2 edges)
__device__ int d_nlist1[N_NODES];
__device__ int d_nlist2[CAP_N2];
__device__ int d_cnt[8];           // 0:n2 1:l2 2:l3 3:n1

struct Seg {
    const float* base;    // row-major [*, K]
    const int*   gather;  // applied to rowlist value; nullptr = value; POS_GATHER = position
    const float* W;       // [K, BN] row-major
    int K;
    int relu;             // relu A elements at staging time
};

__device__ __forceinline__ unsigned long long pack2(float v) {
    unsigned long long r;
    asm("mov.b64 %0, {%1, %1};" : "=l"(r) : "f"(v));
    return r;
}
__device__ __forceinline__ void ffma2(unsigned long long& d,
                                      unsigned long long a,
                                      unsigned long long b) {
    asm("fma.rn.f32x2 %0, %1, %2, %0;" : "+l"(d) : "l"(a), "l"(b));
}
__device__ __forceinline__ float sel2(unsigned long long v, int hi) {
    float2 f = *(float2*)&v; return hi ? f.y : f.x;
}
__device__ __forceinline__ void cp16(uint32_t saddr, const float* g) {
    asm volatile("cp.async.cg.shared.global [%0], [%1], 16;" :: "r"(saddr), "l"(g));
}
__device__ __forceinline__ void cp_commit() {
    asm volatile("cp.async.commit_group;" ::: "memory");
}
__device__ __forceinline__ void cp_wait0() {
    asm volatile("cp.async.wait_group 0;" ::: "memory");
}
__device__ __forceinline__ void redv4(float* p, float4 v) {
    asm volatile("red.global.add.v4.f32 [%0], {%1,%2,%3,%4};"
                 :: "l"(p), "f"(v.x), "f"(v.y), "f"(v.z), "f"(v.w) : "memory");
}

// ---------------- frontier marking / CSR build ----------------

__global__ __launch_bounds__(256) void zero_kernel()
{
    int n4 = N_NODES / 4;
    int4 z = {0, 0, 0, 0};
    for (int i = blockIdx.x * 256 + threadIdx.x; i < n4; i += gridDim.x * 256) {
        ((int4*)d_flag1)[i] = z;
        ((int4*)d_flag2)[i] = z;
        ((int4*)d_deg)[i]   = z;
    }
    if (blockIdx.x == 0 && threadIdx.x < 8) d_cnt[threadIdx.x] = 0;
}

// fused: in-degree count (ALL nodes) + master-edge marking + nlist1 seeding
__global__ __launch_bounds__(256) void mark2_count_scan(
    const int* __restrict__ src, const int* __restrict__ dst)
{
    int n4 = N_EDGES / 4;
    for (int i = blockIdx.x * 256 + threadIdx.x; i < n4; i += gridDim.x * 256) {
        int4 d = ((const int4*)dst)[i];
        int e = i * 4;
        #pragma unroll
        for (int q = 0; q < 4; q++) {
            int dd = (q == 0) ? d.x : (q == 1) ? d.y : (q == 2) ? d.z : d.w;
            atomicAdd(&d_deg[dd], 1);
            if (dd % NODES_PER_GRAPH == 0) {
                int s = src[e + q];
                if (atomicExch(&d_flag2[s], 1) == 0) {
                    d_nlist2[atomicAdd(&d_cnt[0], 1)] = s;
                    if (atomicExch(&d_flag1[s], 1) == 0)
                        d_nlist1[atomicAdd(&d_cnt[3], 1)] = s;
                }
                d_list3[atomicAdd(&d_cnt[2], 1)] = e + q;
            }
        }
    }
    if (blockIdx.x == 0 && threadIdx.x < N_GRAPHS) {
        int v = threadIdx.x * NODES_PER_GRAPH;
        if (atomicExch(&d_flag2[v], 1) == 0) {
            d_nlist2[atomicAdd(&d_cnt[0], 1)] = v;
            if (atomicExch(&d_flag1[v], 1) == 0)
                d_nlist1[atomicAdd(&d_cnt[3], 1)] = v;
        }
    }
}

// ---- coalesced 2-phase exclusive scan of d_deg -> d_off / d_cur ----

__device__ __forceinline__ int block_exscan(int v, int* wsh)
{
    int lane = threadIdx.x & 31, w = threadIdx.x >> 5;
    int s = v;
    #pragma unroll
    for (int o = 1; o < 32; o <<= 1) {
        int n = __shfl_up_sync(0xffffffffu, s, o);
        if (lane >= o) s += n;
    }
    if (lane == 31) wsh[w] = s;
    __syncthreads();
    if (w == 0 && lane < 8) {
        int v8 = wsh[lane];
        #pragma unroll
        for (int o = 1; o < 8; o <<= 1) {
            int n = __shfl_up_sync(0xffu, v8, o);
            if (lane >= o) v8 += n;
        }
        wsh[lane] = v8;
    }
    __syncthreads();
    return s - v + (w ? wsh[w - 1] : 0);
}

__global__ __launch_bounds__(SCAN_B) void scanA_kernel()
{
    __shared__ int sh[SCAN_B];
    int idx = blockIdx.x * SCAN_B + threadIdx.x;
    sh[threadIdx.x] = (idx < N_NODES) ? d_deg[idx] : 0;
    __syncthreads();
    for (int o = 128; o > 0; o >>= 1) {
        if (threadIdx.x < o) sh[threadIdx.x] += sh[threadIdx.x + o];
        __syncthreads();
    }
    if (threadIdx.x == 0) d_bsum[blockIdx.x] = sh[0];
}

__global__ __launch_bounds__(SCAN_B) void scanB_kernel()
{
    __shared__ int wsh[8];
    __shared__ int boff_sh;
    // block offset = sum of bsum[0..blockIdx.x)
    int partial = 0;
    for (int i = threadIdx.x; i < blockIdx.x; i += SCAN_B)
        partial += d_bsum[i];
    #pragma unroll
    for (int o = 16; o > 0; o >>= 1)
        partial += __shfl_down_sync(0xffffffffu, partial, o);
    if ((threadIdx.x & 31) == 0) wsh[threadIdx.x >> 5] = partial;
    __syncthreads();
    if (threadIdx.x == 0) {
        int s = 0;
        #pragma unroll
        for (int w = 0; w < 8; w++) s += wsh[w];
        boff_sh = s;
    }
    __syncthreads();
    int boff = boff_sh;
    int idx = blockIdx.x * SCAN_B + threadIdx.x;
    int v = (idx < N_NODES) ? d_deg[idx] : 0;
    int excl = block_exscan(v, wsh) + boff;
    if (idx < N_NODES) { d_off[idx] = excl; d_cur[idx] = excl; }
}

// scatter all edges into CSR buckets by dst
__global__ __launch_bounds__(256) void scatter_csr_kernel(const int* __restrict__ dst)
{
    int n4 = N_EDGES / 4;
    for (int i = blockIdx.x * 256 + threadIdx.x; i < n4; i += gridDim.x * 256) {
        int4 d = ((const int4*)dst)[i];
        int e = i * 4;
        d_csr[atomicAdd(&d_cur[d.x], 1)] = e + 0;
        d_csr[atomicAdd(&d_cur[d.y], 1)] = e + 1;
        d_csr[atomicAdd(&d_cur[d.z], 1)] = e + 2;
        d_csr[atomicAdd(&d_cur[d.w], 1)] = e + 3;
    }
}

// list2 from CSR: for each flag2 node, its in-edges -> list2 (+pos2);
// sources appended to nlist1 (dedup via flag1)
__global__ __launch_bounds__(256) void list2_csr_kernel(const int* __restrict__ src)
{
    int n = d_cnt[0];
    int lane = threadIdx.x & 31;
    for (int i = blockIdx.x * 8 + (threadIdx.x >> 5); i < n; i += gridDim.x * 8) {
        int v   = d_nlist2[i];
        int beg = d_off[v];
        int dg  = d_deg[v];
        for (int jj = lane; jj < dg; jj += 32) {
            int e = d_csr[beg + jj];
            int j = atomicAdd(&d_cnt[1], 1);
            d_list2[j] = e;
            d_pos2[e]  = j;
            int s = src[e];
            if (atomicExch(&d_flag1[s], 1) == 0)
                d_nlist1[atomicAdd(&d_cnt[3], 1)] = s;
        }
    }
}

// W' = w_proj @ wme1 (128x128); bvec = b_proj @ wme1 (128)
__global__ __launch_bounds__(128) void combine_w_kernel(
    const float* __restrict__ w_proj, const float* __restrict__ b_proj,
    const float* __restrict__ wme1)
{
    int n = threadIdx.x;
    int k = blockIdx.x;
    float s = 0.f;
    if (k < 128) {
        for (int j = 0; j < 64; j++)
            s += w_proj[k * 64 + j] * wme1[j * 128 + n];
        g_wpm[k * 128 + n] = s;
    } else {
        for (int j = 0; j < 64; j++)
            s += b_proj[j] * wme1[j * 128 + n];
        g_bpm[n] = s;
    }
}

// layer-1 aggregation via CSR: warp per flagged node, register accumulation
__global__ __launch_bounds__(256) void agg1_csr_kernel(
    const float* __restrict__ x, const float* __restrict__ eattr,
    const int* __restrict__ src)
{
    int n = d_cnt[3];
    int lane = threadIdx.x & 31;
    for (int i = blockIdx.x * 8 + (threadIdx.x >> 5); i < n; i += gridDim.x * 8) {
        int v   = d_nlist1[i];
        int beg = d_off[v];
        int end = beg + d_deg[v];
        float4 a0 = {0.f, 0.f, 0.f, 0.f}, a1 = a0, aa = a0;
        for (int j = beg; j < end; j++) {
            int e = d_csr[j];
            int s = src[e];
            const float4* xr = (const float4*)(x + (size_t)s * 256);
            float4 u0 = xr[lane];
            float4 u1 = xr[lane + 32];
            a0.x += u0.x; a0.y += u0.y; a0.z += u0.z; a0.w += u0.w;
            a1.x += u1.x; a1.y += u1.y; a1.z += u1.z; a1.w += u1.w;
            float4 w = ((const float4*)(eattr + (size_t)e * 128))[lane];
            aa.x += w.x; aa.y += w.y; aa.z += w.z; aa.w += w.w;
        }
        ((float4*)(g_aggx + (size_t)v * 256))[lane]      = a0;
        ((float4*)(g_aggx + (size_t)v * 256))[lane + 32] = a1;
        ((float4*)(g_agga + (size_t)v * 128))[lane]      = aa;
    }
}

// x1[v] = bs1 + deg[v] * bvec for nlist1 nodes
__global__ __launch_bounds__(256) void seed_x1_kernel(
    float* __restrict__ x1, const float* __restrict__ bs1)
{
    int n = d_cnt[3];
    int total = n * 32;
    for (int i = blockIdx.x * 256 + threadIdx.x; i < total; i += gridDim.x * 256) {
        int r = i >> 5, c = i & 31;
        int v = d_nlist1[r];
        float dg = (float)d_deg[v];
        float4 b = ((const float4*)bs1)[c];
        float4 pv = ((const float4*)g_bpm)[c];
        float4 o = {b.x + dg * pv.x, b.y + dg * pv.y,
                    b.z + dg * pv.z, b.w + dg * pv.w};
        ((float4*)(x1 + (size_t)v * 128))[c] = o;
    }
}

// zero aggx2/agge1 and seed x2 = bs2 for nlist2 nodes
__global__ __launch_bounds__(256) void seed2_kernel(
    float* __restrict__ x2, const float* __restrict__ bs2)
{
    int n = d_cnt[0];
    int total = n * 80;
    float4 z = {0.f, 0.f, 0.f, 0.f};
    for (int i = blockIdx.x * 256 + threadIdx.x; i < total; i += gridDim.x * 256) {
        int r = i / 80, q = i % 80;
        int v = d_nlist2[r];
        if (q < 32)      ((float4*)(g_aggx2 + (size_t)v * 128))[q] = z;
        else if (q < 48) ((float4*)(g_agge1 + (size_t)v * 64))[q - 32] = z;
        else ((float4*)(x2 + (size_t)v * 128))[q - 48] = ((const float4*)bs2)[q - 48];
    }
}

// layer-2 aggregation over list2 positions: red-add relu(x1[src]), e1 (compact)
__global__ __launch_bounds__(256) void agg2_kernel(
    const float* __restrict__ x1,
    const int* __restrict__ src, const int* __restrict__ dst)
{
    int cnt = d_cnt[1];
    int lane = threadIdx.x & 31;
    for (int i = blockIdx.x * 8 + (threadIdx.x >> 5); i < cnt; i += gridDim.x * 8) {
        int e  = d_list2[i];
        int sh = src[e];
        int dh = dst[e];
        float4 v = ((const float4*)(x1 + (size_t)sh * 128))[lane];
        v.x = fmaxf(v.x, 0.f); v.y = fmaxf(v.y, 0.f);
        v.z = fmaxf(v.z, 0.f); v.w = fmaxf(v.w, 0.f);
        redv4(g_aggx2 + (size_t)dh * 128 + lane * 4, v);
        if (lane < 16) {
            float4 u = ((const float4*)(g_e1c + (size_t)i * 64))[lane];
            redv4(g_agge1 + (size_t)dh * 64 + lane * 4, u);
        }
    }
}

// ---------------- pipelined gather-GEMM (f32x2 FMA, 8x8 thread tile) ----------------
// OUT=1: store (+bias,+relu) at scat row; OUT=2: red.global.add at scat row.
template<int BM, int BN, int BK, int NSEG, int OUT>
__global__ __launch_bounds__(256, 2) void gemm_kernel(
    Seg s0, Seg s1, Seg s2,
    const float* __restrict__ bias, int relu_out,
    float* __restrict__ out,
    const int* __restrict__ rowlist,
    const int* __restrict__ scat_map,
    const int* __restrict__ Mptr)
{
    constexpr int ASTR  = BM + 4;
    constexpr int WCOL  = BN / 64;
    constexpr int WPASS = (BK * BN) / 1024;

    const int M    = *Mptr;
    const int row0 = blockIdx.x * BM;
    if (row0 >= M) return;

    extern __shared__ float smem[];
    float* As   = smem;
    float* Wsm  = smem + 2 * BK * ASTR;
    int*   ridx = (int*)(Wsm + 2 * BK * BN);
    int*   sidx = ridx + NSEG * BM;

    Seg segs[3] = {s0, s1, s2};

    const int tid  = threadIdx.x;
    const int warp = tid >> 5;
    const int lane = tid & 31;

    const int wc = warp % WCOL;
    const int wr = warp / WCOL;
    const int ty = wr * 4 + (lane >> 3);
    const int tx = wc * 8 + (lane & 7);

    for (int i = tid; i < BM; i += 256) {
        int r = row0 + i;
        int rc = (r < M) ? r : row0;
        int rid = rowlist[rc];
        #pragma unroll
        for (int s = 0; s < NSEG; s++) {
            const int* g = segs[s].gather;
            ridx[s * BM + i] = (g == POS_GATHER) ? rc : (g ? g[rid] : rid);
        }
        sidx[i] = (scat_map == POS_GATHER) ? rc : (scat_map ? scat_map[rid] : rid);
    }
    __syncthreads();

    const int T0 = segs[0].K / BK;
    const int T1 = T0 + ((NSEG > 1) ? segs[1].K / BK : 0);
    const int T  = T1 + ((NSEG > 2) ? segs[2].K / BK : 0);
    const int ts = T * blockIdx.y / gridDim.y;
    const int te = T * (blockIdx.y + 1) / gridDim.y;

    const int ar_row  = (BM == 256) ? tid : (tid & (BM - 1));
    const int ar_half = (BM == 256) ? 0 : (tid >> 7);

    const float* abase[3];
    #pragma unroll
    for (int s = 0; s < NSEG; s++)
        abase[s] = segs[s].base + (size_t)ridx[s * BM + ar_row] * segs[s].K
                   + ar_half * 16;

    float4 af[4];

    auto map_tile = [&](int t, int& s, int& k0) {
        if (NSEG > 2 && t >= T1)      { s = 2; k0 = (t - T1) * BK; }
        else if (NSEG > 1 && t >= T0) { s = 1; k0 = (t - T0) * BK; }
        else                          { s = 0; k0 = t * BK; }
    };
    auto issueA = [&](int t) {
        int s, k0; map_tile(t, s, k0);
        const float* p = abase[s] + k0;
        #pragma unroll
        for (int q = 0; q < 4; q++) af[q] = *(const float4*)(p + q * 4);
    };
    auto storeA = [&](int t, int buf) {
        int s, k0; map_tile(t, s, k0);
        const int rl = segs[s].relu;
        float* dst = As + buf * (BK * ASTR);
        #pragma unroll
        for (int q = 0; q < 4; q++) {
            float4 v = af[q];
            if (rl) {
                v.x = fmaxf(v.x, 0.f); v.y = fmaxf(v.y, 0.f);
                v.z = fmaxf(v.z, 0.f); v.w = fmaxf(v.w, 0.f);
            }
            int kk = ar_half * 16 + q * 4;
            dst[(kk + 0) * ASTR + ar_row] = v.x;
            dst[(kk + 1) * ASTR + ar_row] = v.y;
            dst[(kk + 2) * ASTR + ar_row] = v.z;
            dst[(kk + 3) * ASTR + ar_row] = v.w;
        }
    };
    auto issueW = [&](int t, int buf) {
        int s, k0; map_tile(t, s, k0);
        const float* wp = segs[s].W + (size_t)k0 * BN;
        uint32_t sa = (uint32_t)__cvta_generic_to_shared(Wsm + buf * (BK * BN));
        #pragma unroll
        for (int ps = 0; ps < WPASS; ps++) {
            int i = tid * 4 + ps * 1024;
            cp16(sa + i * 4, wp + i);
        }
    };

    unsigned long long acc2[4][8];
    #pragma unroll
    for (int p = 0; p < 4; p++)
        #pragma unroll
        for (int j = 0; j < 8; j++) acc2[p][j] = 0ull;

    issueA(ts); storeA(ts, 0); issueW(ts, 0); cp_commit();
    if (ts + 1 < te) issueA(ts + 1);
    cp_wait0();
    __syncthreads();

    for (int t = ts; t < te; t++) {
        int buf = (t - ts) & 1;
        if (t + 1 < te) { issueW(t + 1, buf ^ 1); cp_commit(); storeA(t + 1, buf ^ 1); }
        if (t + 2 < te) issueA(t + 2);

        const float* as = As  + buf * (BK * ASTR);
        const float* ws = Wsm + buf * (BK * BN);
        #pragma unroll
        for (int k = 0; k < BK; k++) {
            ulonglong2 alo = *(const ulonglong2*)(as + k * ASTR + ty * 4);
            ulonglong2 ahi = *(const ulonglong2*)(as + k * ASTR + BM / 2 + ty * 4);
            float4 wlo = *(const float4*)(ws + k * BN + tx * 4);
            float4 whi = *(const float4*)(ws + k * BN + BN / 2 + tx * 4);
            unsigned long long ar[4] = {alo.x, alo.y, ahi.x, ahi.y};
            unsigned long long bd[8] = {
                pack2(wlo.x), pack2(wlo.y), pack2(wlo.z), pack2(wlo.w),
                pack2(whi.x), pack2(whi.y), pack2(whi.z), pack2(whi.w)};
            #pragma unroll
            for (int p = 0; p < 4; p++)
                #pragma unroll
                for (int j = 0; j < 8; j++)
                    ffma2(acc2[p][j], ar[p], bd[j]);
        }
        cp_wait0();
        __syncthreads();
    }

    float bv[8];
    if (OUT == 1) {
        #pragma unroll
        for (int j = 0; j < 4; j++) {
            bv[j]     = bias ? bias[tx * 4 + j] : 0.f;
            bv[4 + j] = bias ? bias[BN / 2 + tx * 4 + j] : 0.f;
        }
    }
    #pragma unroll
    for (int h = 0; h < 8; h++) {
        int hh = h & 3;
        int p  = ((h >> 2) << 1) | (hh >> 1);
        int c  = hh & 1;
        int rl = (h < 4) ? (ty * 4 + hh) : (BM / 2 + ty * 4 + hh);
        if (row0 + rl < M) {
            float* op = out + (size_t)sidx[rl] * BN;
            if (OUT == 2) {
                float v0 = sel2(acc2[p][0], c), v1 = sel2(acc2[p][1], c);
                float v2 = sel2(acc2[p][2], c), v3 = sel2(acc2[p][3], c);
                asm volatile("red.global.add.v4.f32 [%0], {%1,%2,%3,%4};"
                             :: "l"(op + tx * 4), "f"(v0), "f"(v1), "f"(v2), "f"(v3)
                             : "memory");
                float u0 = sel2(acc2[p][4], c), u1 = sel2(acc2[p][5], c);
                float u2 = sel2(acc2[p][6], c), u3 = sel2(acc2[p][7], c);
                asm volatile("red.global.add.v4.f32 [%0], {%1,%2,%3,%4};"
                             :: "l"(op + BN / 2 + tx * 4), "f"(u0), "f"(u1), "f"(u2), "f"(u3)
                             : "memory");
            } else {
                float4 o0, o1;
                o0.x = sel2(acc2[p][0], c) + bv[0];
                o0.y = sel2(acc2[p][1], c) + bv[1];
                o0.z = sel2(acc2[p][2], c) + bv[2];
                o0.w = sel2(acc2[p][3], c) + bv[3];
                o1.x = sel2(acc2[p][4], c) + bv[4];
                o1.y = sel2(acc2[p][5], c) + bv[5];
                o1.z = sel2(acc2[p][6], c) + bv[6];
                o1.w = sel2(acc2[p][7], c) + bv[7];
                if (relu_out) {
                    o0.x = fmaxf(o0.x, 0.f); o0.y = fmaxf(o0.y, 0.f);
                    o0.z = fmaxf(o0.z, 0.f); o0.w = fmaxf(o0.w, 0.f);
                    o1.x = fmaxf(o1.x, 0.f); o1.y = fmaxf(o1.y, 0.f);
                    o1.z = fmaxf(o1.z, 0.f); o1.w = fmaxf(o1.w, 0.f);
                }
                *(float4*)(op + tx * 4) = o0;
                *(float4*)(op + BN / 2 + tx * 4) = o1;
            }
        }
    }
}

// ---------------- layer-3 master kernels ----------------

__global__ __launch_bounds__(256) void master_node_kernel(
    const float* __restrict__ x2, const float* __restrict__ ws3,
    const float* __restrict__ bs3, float* __restrict__ out)
{
    int g = blockIdx.x;
    int c = threadIdx.x;
    const float* xr = x2 + (size_t)g * NODES_PER_GRAPH * 128;
    float acc = bs3[c];
    #pragma unroll 8
    for (int k = 0; k < 128; k++)
        acc += fmaxf(xr[k], 0.f) * ws3[(size_t)k * 256 + c];
    out[(size_t)g * 256 + c] = acc;
}

// out[g] += relu_x2[src]@wmx3 + e2@wme3 over list3 positions (warp per edge)
__global__ __launch_bounds__(256) void master_edge3_kernel(
    const float* __restrict__ x2,
    const int* __restrict__ src, const int* __restrict__ dst,
    const float* __restrict__ wmx3, const float* __restrict__ wme3,
    float* __restrict__ out)
{
    int cnt = d_cnt[2];
    int lane = threadIdx.x & 31;
    for (int i = blockIdx.x * 8 + (threadIdx.x >> 5); i < cnt; i += gridDim.x * 8) {
        int e  = d_list3[i];
        int sh = src[e];
        int g  = dst[e] / NODES_PER_GRAPH;
        float acc[8];
        #pragma unroll
        for (int j = 0; j < 8; j++) acc[j] = 0.f;
        const float* xr = x2 + (size_t)sh * 128;
        for (int k = 0; k < 128; k++) {
            float a = fmaxf(xr[k], 0.f);
            const float* wr = wmx3 + (size_t)k * 256;
            #pragma unroll
            for (int j = 0; j < 8; j++) acc[j] += a * wr[lane + j * 32];
        }
        const float* er = g_e2c + (size_t)i * 64;
        for (int k = 0; k < 64; k++) {
            float a = er[k];
            const float* wr = wme3 + (size_t)k * 256;
            #pragma unroll
            for (int j = 0; j < 8; j++) acc[j] += a * wr[lane + j * 32];
        }
        float* op = out + (size_t)g * 256;
        #pragma unroll
        for (int j = 0; j < 8; j++) atomicAdd(op + lane + j * 32, acc[j]);
    }
}

template<int BM, int BN, int BK, int NSEG>
static int smem_bytes() {
    constexpr int ASTR = BM + 4;
    return (2 * BK * ASTR + 2 * BK * BN) * 4 + NSEG * BM * 4 + BM * 4;
}

extern "C" void kernel_launch(void* const* d_in, const int* in_sizes, int n_in,
                              void* d_out, int out_size)
{
    const float* x         = (const float*)d_in[0];
    const int*   edge_idx  = (const int*)d_in[1];
    const float* edge_attr = (const float*)d_in[2];
    const float* w_proj    = (const float*)d_in[4];
    const float* b_proj    = (const float*)d_in[5];
    const float* P[30];
    for (int i = 0; i < 30 && i < n_in; i++) P[i] = (const float*)d_in[i];

    const int* src = edge_idx;
    const int* dst = edge_idx + N_EDGES;
    float* out = (float*)d_out;

    void* p;
    cudaGetSymbolAddress(&p, g_x1);     float* x1_p    = (float*)p;
    cudaGetSymbolAddress(&p, g_x2);     float* x2_p    = (float*)p;
    cudaGetSymbolAddress(&p, g_aggx);   float* aggx_p  = (float*)p;
    cudaGetSymbolAddress(&p, g_agga);   float* agga_p  = (float*)p;
    cudaGetSymbolAddress(&p, g_aggx2);  float* aggx2_p = (float*)p;
    cudaGetSymbolAddress(&p, g_agge1);  float* agge1_p = (float*)p;
    cudaGetSymbolAddress(&p, g_ec);     float* ec_p    = (float*)p;
    cudaGetSymbolAddress(&p, g_e1c);    float* e1c_p   = (float*)p;
    cudaGetSymbolAddress(&p, g_e2c);    float* e2c_p   = (float*)p;
    cudaGetSymbolAddress(&p, g_wpm);    float* wpm_p   = (float*)p;
    cudaGetSymbolAddress(&p, d_list2);  const int* l2  = (const int*)p;
    cudaGetSymbolAddress(&p, d_list3);  const int* l3  = (const int*)p;
    cudaGetSymbolAddress(&p, d_pos2);   const int* pos2 = (const int*)p;
    cudaGetSymbolAddress(&p, d_nlist1); const int* n1  = (const int*)p;
    cudaGetSymbolAddress(&p, d_nlist2); const int* n2  = (const int*)p;
    cudaGetSymbolAddress(&p, d_cnt);    const int* cnt = (const int*)p;
    const int* c_n2 = cnt + 0;
    const int* c_l2 = cnt + 1;
    const int* c_l3 = cnt + 2;
    const int* c_n1 = cnt + 3;

    static cudaStream_t sB = nullptr, sC = nullptr, sD = nullptr;
    static cudaEvent_t evRoot, evCW, evMark, evCSR, evL2C, evSeed, evG1,
                       evS2, evE1, evX1, evE2;
    if (!sB) {
        cudaFuncSetAttribute(gemm_kernel<256, 64, 16, 1, 1>,
            cudaFuncAttributeMaxDynamicSharedMemorySize, smem_bytes<256, 64, 16, 1>());
        cudaFuncSetAttribute(gemm_kernel<256, 64, 16, 3, 1>,
            cudaFuncAttributeMaxDynamicSharedMemorySize, smem_bytes<256, 64, 16, 3>());
        cudaFuncSetAttribute(gemm_kernel<128, 128, 32, 1, 2>,
            cudaFuncAttributeMaxDynamicSharedMemorySize, smem_bytes<128, 128, 32, 1>());
        cudaFuncSetAttribute(gemm_kernel<128, 128, 32, 2, 2>,
            cudaFuncAttributeMaxDynamicSharedMemorySize, smem_bytes<128, 128, 32, 2>());
        cudaFuncSetAttribute(gemm_kernel<128, 128, 32, 3, 2>,
            cudaFuncAttributeMaxDynamicSharedMemorySize, smem_bytes<128, 128, 32, 3>());
        cudaStreamCreateWithFlags(&sB, cudaStreamNonBlocking);
        cudaStreamCreateWithFlags(&sC, cudaStreamNonBlocking);
        cudaStreamCreateWithFlags(&sD, cudaStreamNonBlocking);
        cudaEventCreateWithFlags(&evRoot, cudaEventDisableTiming);
        cudaEventCreateWithFlags(&evCW,   cudaEventDisableTiming);
        cudaEventCreateWithFlags(&evMark, cudaEventDisableTiming);
        cudaEventCreateWithFlags(&evCSR,  cudaEventDisableTiming);
        cudaEventCreateWithFlags(&evL2C,  cudaEventDisableTiming);
        cudaEventCreateWithFlags(&evSeed, cudaEventDisableTiming);
        cudaEventCreateWithFlags(&evG1,   cudaEventDisableTiming);
        cudaEventCreateWithFlags(&evS2,   cudaEventDisableTiming);
        cudaEventCreateWithFlags(&evE1,   cudaEventDisableTiming);
        cudaEventCreateWithFlags(&evX1,   cudaEventDisableTiming);
        cudaEventCreateWithFlags(&evE2,   cudaEventDisableTiming);
    }

    Seg z = {nullptr, nullptr, nullptr, 0, 0};

    // ---- fork root: stream C does combine_w concurrently with marking ----
    cudaEventRecord(evRoot, 0);
    cudaStreamWaitEvent(sC, evRoot, 0);
    combine_w_kernel<<<129, 128, 0, sC>>>(w_proj, b_proj, P[9]);   // P[9]=wme1
    cudaEventRecord(evCW, sC);

    // ---- chain A: marking (+ fused degree count + nlist1 seed) ----
    zero_kernel<<<256, 256>>>();
    mark2_count_scan<<<1024, 256>>>(src, dst);
    cudaEventRecord(evMark, 0);

    // ---- stream D: CSR build ----
    cudaStreamWaitEvent(sD, evMark, 0);
    scanA_kernel<<<SCAN_NB, SCAN_B, 0, sD>>>();
    scanB_kernel<<<SCAN_NB, SCAN_B, 0, sD>>>();
    scatter_csr_kernel<<<1024, 256, 0, sD>>>(dst);
    cudaEventRecord(evCSR, sD);

    // ---- stream C: seed2 (needs nlist2) ----
    cudaStreamWaitEvent(sC, evMark, 0);
    seed2_kernel<<<256, 256, 0, sC>>>(x2_p, P[15]);
    cudaEventRecord(evS2, sC);

    // ---- chain A: list2 from CSR (completes nlist1/flag1) ----
    cudaStreamWaitEvent(0, evCSR, 0);
    list2_csr_kernel<<<64, 256>>>(src);
    cudaEventRecord(evL2C, 0);

    // ---- stream D: seed x1 then G1 = x@ws1 (red-add), overlaps agg1 ----
    cudaStreamWaitEvent(sD, evL2C, 0);
    cudaStreamWaitEvent(sD, evCW, 0);
    seed_x1_kernel<<<512, 256, 0, sD>>>(x1_p, P[7]);
    cudaEventRecord(evSeed, sD);
    {
        Seg a = {x, nullptr, P[6], 256, 0};
        gemm_kernel<128, 128, 32, 1, 2>
            <<<dim3(CAP_N1 / 128, 1), 256, smem_bytes<128, 128, 32, 1>(), sD>>>(
            a, z, z, nullptr, 0, x1_p, n1, nullptr, c_n1);
    }
    cudaEventRecord(evG1, sD);

    // ---- chain B: e0 -> e1 (single-pass, fused bias+relu) ----
    cudaStreamWaitEvent(sB, evL2C, 0);
    {
        Seg a = {edge_attr, nullptr, w_proj, 128, 0};
        gemm_kernel<256, 64, 16, 1, 1>
            <<<CAP_L2 / 256, 256, smem_bytes<256, 64, 16, 1>(), sB>>>(
            a, z, z, b_proj, 0, ec_p, l2, POS_GATHER, c_l2);
    }
    {
        Seg a = {x,    src,        P[10], 256, 0};
        Seg b = {x,    dst,        P[11], 256, 0};
        Seg c = {ec_p, POS_GATHER, P[12], 64,  0};
        gemm_kernel<256, 64, 16, 3, 1>
            <<<CAP_L2 / 256, 256, smem_bytes<256, 64, 16, 3>(), sB>>>(
            a, b, c, P[13], 1, e1c_p, l2, POS_GATHER, c_l2);
    }
    cudaEventRecord(evE1, sB);

    // ---- chain A: CSR aggregation + G2 (x1 stays pre-relu in memory) ----
    agg1_csr_kernel<<<2048, 256>>>(x, edge_attr, src);
    cudaStreamWaitEvent(0, evSeed, 0);
    {
        Seg a = {aggx_p, nullptr, P[8],  256, 0};
        Seg b = {agga_p, nullptr, wpm_p, 128, 0};
        gemm_kernel<128, 128, 32, 2, 2>
            <<<dim3(CAP_N1 / 128, 2), 256, smem_bytes<128, 128, 32, 2>()>>>(
            a, b, z, nullptr, 0, x1_p, n1, nullptr, c_n1);
    }
    cudaStreamWaitEvent(0, evG1, 0);
    cudaEventRecord(evX1, 0);                    // x1 final (pre-relu)

    // ---- chain B: e2 (relu(x1) on load; single-pass bias+relu) ----
    cudaStreamWaitEvent(sB, evX1, 0);
    {
        Seg a = {x1_p,  src,   P[18], 128, 1};
        Seg b = {x1_p,  dst,   P[19], 128, 1};
        Seg c = {e1c_p, pos2,  P[20], 64,  0};
        gemm_kernel<256, 64, 16, 3, 1>
            <<<CAP_L3 / 256, 256, smem_bytes<256, 64, 16, 3>(), sB>>>(
            a, b, c, P[21], 1, e2c_p, l3, POS_GATHER, c_l3);
    }
    cudaEventRecord(evE2, sB);

    // ---- chain A: layer 2 + masters ----
    cudaStreamWaitEvent(0, evE1, 0);
    cudaStreamWaitEvent(0, evS2, 0);
    agg2_kernel<<<512, 256>>>(x1_p, src, dst);   // relu applied inline
    {
        Seg a = {x1_p,    nullptr, P[14], 128, 1};
        Seg b = {aggx2_p, nullptr, P[16], 128, 0};
        Seg c = {agge1_p, nullptr, P[17], 64,  0};
        gemm_kernel<128, 128, 32, 3, 2>
            <<<dim3(CAP_N2 / 128, 4), 256, smem_bytes<128, 128, 32, 3>()>>>(
            a, b, c, nullptr, 0, x2_p, n2, nullptr, c_n2);
    }
    master_node_kernel<<<N_GRAPHS, 256>>>(x2_p, P[22], P[23], out);
    cudaStreamWaitEvent(0, evE2, 0);
    master_edge3_kernel<<<128, 256>>>(x2_p, src, dst, P[24], P[25], out);
}

// round 14
// speedup vs baseline: 1.0612x; 1.0612x over previous
#include <cuda_runtime.h>
#include <cstddef>
#include <cstdint>

#define N_NODES 50000
#define N_EDGES 800000
#define N_GRAPHS 50
#define NODES_PER_GRAPH 1000

#define CAP_L2 32768      // edges into flag2 nodes (expected ~13.4K)
#define CAP_L3 4096       // master-destination edges (expected ~800)
#define CAP_N1 24576      // nodes needing x1 (expected ~14.2K)
#define CAP_N2 4096       // nodes needing x2 (expected ~850)

#define POS_GATHER ((const int*)(size_t)1)   // sentinel: use list position as row

#define SCAN_B 256
#define SCAN_NB ((N_NODES + SCAN_B - 1) / SCAN_B)   // 196

// Scratch (device globals; allocation rules forbid cudaMalloc)
__device__ float g_x1[(size_t)N_NODES * 128];
__device__ float g_x2[(size_t)N_NODES * 128];
__device__ float g_aggx[(size_t)N_NODES * 256];    // sum x[src] per dst (layer 1)
__device__ float g_agga[(size_t)N_NODES * 128];    // sum edge_attr per dst (layer 1)
__device__ float g_aggx2[(size_t)N_NODES * 128];   // sum relu_x1[src] per dst (layer 2)
__device__ float g_agge1[(size_t)N_NODES * 64];    // sum e1 per dst (layer 2)
__device__ float g_ec[(size_t)CAP_L2 * 64];        // e0 rows, list2-position indexed
__device__ float g_e1c[(size_t)CAP_L2 * 64];       // e1 rows, list2-position indexed
__device__ float g_e2c[(size_t)CAP_L3 * 64];       // e2 rows, list3-position indexed
__device__ float g_wpm[128 * 128];                 // w_proj @ wme1
__device__ float g_bpm[128];                       // b_proj @ wme1

__device__ int d_flag1[N_NODES];
__device__ int d_flag2[N_NODES];
__device__ int d_deg[N_NODES];     // FULL in-degree of every node
__device__ int d_off[N_NODES];     // CSR exclusive offsets
__device__ int d_cur[N_NODES];     // scatter cursors
__device__ int d_csr[N_EDGES];     // edge ids grouped by dst
__device__ int d_bsum[SCAN_NB];    // per-block sums for scan
__device__ int d_list2[CAP_L2];
__device__ int d_list3[CAP_L3];
__device__ int d_pos2[N_EDGES];    // edge id -> list2 position (valid for list2 edges)
__device__ int d_nlist1[N_NODES];
__device__ int d_nlist2[CAP_N2];
__device__ int d_cnt[8];           // 0:n2 1:l2 2:l3 3:n1

struct Seg {
    const float* base;    // row-major [*, K]
    const int*   gather;  // applied to rowlist value; nullptr = value; POS_GATHER = position
    const float* W;       // [K, BN] row-major
    int K;
    int relu;             // relu A elements at staging time
};

__device__ __forceinline__ unsigned long long pack2(float v) {
    unsigned long long r;
    asm("mov.b64 %0, {%1, %1};" : "=l"(r) : "f"(v));
    return r;
}
__device__ __forceinline__ void ffma2(unsigned long long& d,
                                      unsigned long long a,
                                      unsigned long long b) {
    asm("fma.rn.f32x2 %0, %1, %2, %0;" : "+l"(d) : "l"(a), "l"(b));
}
__device__ __forceinline__ float sel2(unsigned long long v, int hi) {
    float2 f = *(float2*)&v; return hi ? f.y : f.x;
}
__device__ __forceinline__ void cp16(uint32_t saddr, const float* g) {
    asm volatile("cp.async.cg.shared.global [%0], [%1], 16;" :: "r"(saddr), "l"(g));
}
__device__ __forceinline__ void cp_commit() {
    asm volatile("cp.async.commit_group;" ::: "memory");
}
__device__ __forceinline__ void cp_wait0() {
    asm volatile("cp.async.wait_group 0;" ::: "memory");
}
__device__ __forceinline__ void redv4(float* p, float4 v) {
    asm volatile("red.global.add.v4.f32 [%0], {%1,%2,%3,%4};"
                 :: "l"(p), "f"(v.x), "f"(v.y), "f"(v.z), "f"(v.w) : "memory");
}

// ---------------- frontier marking / CSR build ----------------

__global__ __launch_bounds__(256) void zero_kernel()
{
    int n4 = N_NODES / 4;
    int4 z = {0, 0, 0, 0};
    for (int i = blockIdx.x * 256 + threadIdx.x; i < n4; i += gridDim.x * 256) {
        ((int4*)d_flag1)[i] = z;
        ((int4*)d_flag2)[i] = z;
        ((int4*)d_deg)[i]   = z;
    }
    if (blockIdx.x == 0 && threadIdx.x < 8) d_cnt[threadIdx.x] = 0;
}

// fused: in-degree count (ALL nodes) + master-edge marking + nlist1/2 seeding
__global__ __launch_bounds__(256) void mark2_count_scan(
    const int* __restrict__ src, const int* __restrict__ dst)
{
    int n4 = N_EDGES / 4;
    for (int i = blockIdx.x * 256 + threadIdx.x; i < n4; i += gridDim.x * 256) {
        int4 d = ((const int4*)dst)[i];
        int e = i * 4;
        #pragma unroll
        for (int q = 0; q < 4; q++) {
            int dd = (q == 0) ? d.x : (q == 1) ? d.y : (q == 2) ? d.z : d.w;
            atomicAdd(&d_deg[dd], 1);
            if (dd % NODES_PER_GRAPH == 0) {
                int s = src[e + q];
                if (atomicExch(&d_flag2[s], 1) == 0) {
                    d_nlist2[atomicAdd(&d_cnt[0], 1)] = s;
                    if (atomicExch(&d_flag1[s], 1) == 0)
                        d_nlist1[atomicAdd(&d_cnt[3], 1)] = s;
                }
                d_list3[atomicAdd(&d_cnt[2], 1)] = e + q;
            }
        }
    }
    if (blockIdx.x == 0 && threadIdx.x < N_GRAPHS) {
        int v = threadIdx.x * NODES_PER_GRAPH;
        if (atomicExch(&d_flag2[v], 1) == 0) {
            d_nlist2[atomicAdd(&d_cnt[0], 1)] = v;
            if (atomicExch(&d_flag1[v], 1) == 0)
                d_nlist1[atomicAdd(&d_cnt[3], 1)] = v;
        }
    }
}

// edges into flag2 nodes -> list2 (+pos2); sources appended to nlist1 (dedup)
__global__ __launch_bounds__(256) void list2_scan(
    const int* __restrict__ src, const int* __restrict__ dst)
{
    int n4 = N_EDGES / 4;
    for (int i = blockIdx.x * 256 + threadIdx.x; i < n4; i += gridDim.x * 256) {
        int4 d = ((const int4*)dst)[i];
        int e = i * 4;
        #pragma unroll
        for (int q = 0; q < 4; q++) {
            int dd = (q == 0) ? d.x : (q == 1) ? d.y : (q == 2) ? d.z : d.w;
            int ee = e + q;
            if (d_flag2[dd]) {
                int j = atomicAdd(&d_cnt[1], 1);
                d_list2[j] = ee;
                d_pos2[ee] = j;
                int s = src[ee];
                if (atomicExch(&d_flag1[s], 1) == 0)
                    d_nlist1[atomicAdd(&d_cnt[3], 1)] = s;
            }
        }
    }
}

// ---- coalesced 2-phase exclusive scan of d_deg -> d_off / d_cur ----

__device__ __forceinline__ int block_exscan(int v, int* wsh)
{
    int lane = threadIdx.x & 31, w = threadIdx.x >> 5;
    int s = v;
    #pragma unroll
    for (int o = 1; o < 32; o <<= 1) {
        int n = __shfl_up_sync(0xffffffffu, s, o);
        if (lane >= o) s += n;
    }
    if (lane == 31) wsh[w] = s;
    __syncthreads();
    if (w == 0 && lane < 8) {
        int v8 = wsh[lane];
        #pragma unroll
        for (int o = 1; o < 8; o <<= 1) {
            int n = __shfl_up_sync(0xffu, v8, o);
            if (lane >= o) v8 += n;
        }
        wsh[lane] = v8;
    }
    __syncthreads();
    return s - v + (w ? wsh[w - 1] : 0);
}

__global__ __launch_bounds__(SCAN_B) void scanA_kernel()
{
    __shared__ int sh[SCAN_B];
    int idx = blockIdx.x * SCAN_B + threadIdx.x;
    sh[threadIdx.x] = (idx < N_NODES) ? d_deg[idx] : 0;
    __syncthreads();
    for (int o = 128; o > 0; o >>= 1) {
        if (threadIdx.x < o) sh[threadIdx.x] += sh[threadIdx.x + o];
        __syncthreads();
    }
    if (threadIdx.x == 0) d_bsum[blockIdx.x] = sh[0];
}

__global__ __launch_bounds__(SCAN_B) void scanB_kernel()
{
    __shared__ int wsh[8];
    __shared__ int boff_sh;
    int partial = 0;
    for (int i = threadIdx.x; i < blockIdx.x; i += SCAN_B)
        partial += d_bsum[i];
    #pragma unroll
    for (int o = 16; o > 0; o >>= 1)
        partial += __shfl_down_sync(0xffffffffu, partial, o);
    if ((threadIdx.x & 31) == 0) wsh[threadIdx.x >> 5] = partial;
    __syncthreads();
    if (threadIdx.x == 0) {
        int s = 0;
        #pragma unroll
        for (int w = 0; w < 8; w++) s += wsh[w];
        boff_sh = s;
    }
    __syncthreads();
    int boff = boff_sh;
    int idx = blockIdx.x * SCAN_B + threadIdx.x;
    int v = (idx < N_NODES) ? d_deg[idx] : 0;
    int excl = block_exscan(v, wsh) + boff;
    if (idx < N_NODES) { d_off[idx] = excl; d_cur[idx] = excl; }
}

// scatter all edges into CSR buckets by dst
__global__ __launch_bounds__(256) void scatter_csr_kernel(const int* __restrict__ dst)
{
    int n4 = N_EDGES / 4;
    for (int i = blockIdx.x * 256 + threadIdx.x; i < n4; i += gridDim.x * 256) {
        int4 d = ((const int4*)dst)[i];
        int e = i * 4;
        d_csr[atomicAdd(&d_cur[d.x], 1)] = e + 0;
        d_csr[atomicAdd(&d_cur[d.y], 1)] = e + 1;
        d_csr[atomicAdd(&d_cur[d.z], 1)] = e + 2;
        d_csr[atomicAdd(&d_cur[d.w], 1)] = e + 3;
    }
}

// W' = w_proj @ wme1 (128x128); bvec = b_proj @ wme1 (128)
__global__ __launch_bounds__(128) void combine_w_kernel(
    const float* __restrict__ w_proj, const float* __restrict__ b_proj,
    const float* __restrict__ wme1)
{
    int n = threadIdx.x;
    int k = blockIdx.x;
    float s = 0.f;
    if (k < 128) {
        for (int j = 0; j < 64; j++)
            s += w_proj[k * 64 + j] * wme1[j * 128 + n];
        g_wpm[k * 128 + n] = s;
    } else {
        for (int j = 0; j < 64; j++)
            s += b_proj[j] * wme1[j * 128 + n];
        g_bpm[n] = s;
    }
}

// layer-1 aggregation via CSR: warp per flagged node, register accumulation
__global__ __launch_bounds__(256) void agg1_csr_kernel(
    const float* __restrict__ x, const float* __restrict__ eattr,
    const int* __restrict__ src)
{
    int n = d_cnt[3];
    int lane = threadIdx.x & 31;
    for (int i = blockIdx.x * 8 + (threadIdx.x >> 5); i < n; i += gridDim.x * 8) {
        int v   = d_nlist1[i];
        int beg = d_off[v];
        int end = beg + d_deg[v];
        float4 a0 = {0.f, 0.f, 0.f, 0.f}, a1 = a0, aa = a0;
        for (int j = beg; j < end; j++) {
            int e = d_csr[j];
            int s = src[e];
            const float4* xr = (const float4*)(x + (size_t)s * 256);
            float4 u0 = xr[lane];
            float4 u1 = xr[lane + 32];
            a0.x += u0.x; a0.y += u0.y; a0.z += u0.z; a0.w += u0.w;
            a1.x += u1.x; a1.y += u1.y; a1.z += u1.z; a1.w += u1.w;
            float4 w = ((const float4*)(eattr + (size_t)e * 128))[lane];
            aa.x += w.x; aa.y += w.y; aa.z += w.z; aa.w += w.w;
        }
        ((float4*)(g_aggx + (size_t)v * 256))[lane]      = a0;
        ((float4*)(g_aggx + (size_t)v * 256))[lane + 32] = a1;
        ((float4*)(g_agga + (size_t)v * 128))[lane]      = aa;
    }
}

// x1[v] = bs1 + deg[v] * bvec for nlist1 nodes
__global__ __launch_bounds__(256) void seed_x1_kernel(
    float* __restrict__ x1, const float* __restrict__ bs1)
{
    int n = d_cnt[3];
    int total = n * 32;
    for (int i = blockIdx.x * 256 + threadIdx.x; i < total; i += gridDim.x * 256) {
        int r = i >> 5, c = i & 31;
        int v = d_nlist1[r];
        float dg = (float)d_deg[v];
        float4 b = ((const float4*)bs1)[c];
        float4 pv = ((const float4*)g_bpm)[c];
        float4 o = {b.x + dg * pv.x, b.y + dg * pv.y,
                    b.z + dg * pv.z, b.w + dg * pv.w};
        ((float4*)(x1 + (size_t)v * 128))[c] = o;
    }
}

// zero aggx2/agge1 and seed x2 = bs2 for nlist2 nodes
__global__ __launch_bounds__(256) void seed2_kernel(
    float* __restrict__ x2, const float* __restrict__ bs2)
{
    int n = d_cnt[0];
    int total = n * 80;
    float4 z = {0.f, 0.f, 0.f, 0.f};
    for (int i = blockIdx.x * 256 + threadIdx.x; i < total; i += gridDim.x * 256) {
        int r = i / 80, q = i % 80;
        int v = d_nlist2[r];
        if (q < 32)      ((float4*)(g_aggx2 + (size_t)v * 128))[q] = z;
        else if (q < 48) ((float4*)(g_agge1 + (size_t)v * 64))[q - 32] = z;
        else ((float4*)(x2 + (size_t)v * 128))[q - 48] = ((const float4*)bs2)[q - 48];
    }
}

// layer-2 aggregation over list2 positions: red-add relu(x1[src]), e1 (compact)
__global__ __launch_bounds__(256) void agg2_kernel(
    const float* __restrict__ x1,
    const int* __restrict__ src, const int* __restrict__ dst)
{
    int cnt = d_cnt[1];
    int lane = threadIdx.x & 31;
    for (int i = blockIdx.x * 8 + (threadIdx.x >> 5); i < cnt; i += gridDim.x * 8) {
        int e  = d_list2[i];
        int sh = src[e];
        int dh = dst[e];
        float4 v = ((const float4*)(x1 + (size_t)sh * 128))[lane];
        v.x = fmaxf(v.x, 0.f); v.y = fmaxf(v.y, 0.f);
        v.z = fmaxf(v.z, 0.f); v.w = fmaxf(v.w, 0.f);
        redv4(g_aggx2 + (size_t)dh * 128 + lane * 4, v);
        if (lane < 16) {
            float4 u = ((const float4*)(g_e1c + (size_t)i * 64))[lane];
            redv4(g_agge1 + (size_t)dh * 64 + lane * 4, u);
        }
    }
}

// ---------------- pipelined gather-GEMM (f32x2 FMA, 8x8 thread tile) ----------------
// OUT=1: store (+bias,+relu) at scat row; OUT=2: red.global.add at scat row.
template<int BM, int BN, int BK, int NSEG, int OUT>
__global__ __launch_bounds__(256, 2) void gemm_kernel(
    Seg s0, Seg s1, Seg s2,
    const float* __restrict__ bias, int relu_out,
    float* __restrict__ out,
    const int* __restrict__ rowlist,
    const int* __restrict__ scat_map,
    const int* __restrict__ Mptr)
{
    constexpr int ASTR  = BM + 4;
    constexpr int WCOL  = BN / 64;
    constexpr int WPASS = (BK * BN) / 1024;

    const int M    = *Mptr;
    const int row0 = blockIdx.x * BM;
    if (row0 >= M) return;

    extern __shared__ float smem[];
    float* As   = smem;
    float* Wsm  = smem + 2 * BK * ASTR;
    int*   ridx = (int*)(Wsm + 2 * BK * BN);
    int*   sidx = ridx + NSEG * BM;

    Seg segs[3] = {s0, s1, s2};

    const int tid  = threadIdx.x;
    const int warp = tid >> 5;
    const int lane = tid & 31;

    const int wc = warp % WCOL;
    const int wr = warp / WCOL;
    const int ty = wr * 4 + (lane >> 3);
    const int tx = wc * 8 + (lane & 7);

    for (int i = tid; i < BM; i += 256) {
        int r = row0 + i;
        int rc = (r < M) ? r : row0;
        int rid = rowlist[rc];
        #pragma unroll
        for (int s = 0; s < NSEG; s++) {
            const int* g = segs[s].gather;
            ridx[s * BM + i] = (g == POS_GATHER) ? rc : (g ? g[rid] : rid);
        }
        sidx[i] = (scat_map == POS_GATHER) ? rc : (scat_map ? scat_map[rid] : rid);
    }
    __syncthreads();

    const int T0 = segs[0].K / BK;
    const int T1 = T0 + ((NSEG > 1) ? segs[1].K / BK : 0);
    const int T  = T1 + ((NSEG > 2) ? segs[2].K / BK : 0);
    const int ts = T * blockIdx.y / gridDim.y;
    const int te = T * (blockIdx.y + 1) / gridDim.y;

    const int ar_row  = (BM == 256) ? tid : (tid & (BM - 1));
    const int ar_half = (BM == 256) ? 0 : (tid >> 7);

    const float* abase[3];
    #pragma unroll
    for (int s = 0; s < NSEG; s++)
        abase[s] = segs[s].base + (size_t)ridx[s * BM + ar_row] * segs[s].K
                   + ar_half * 16;

    float4 af[4];

    auto map_tile = [&](int t, int& s, int& k0) {
        if (NSEG > 2 && t >= T1)      { s = 2; k0 = (t - T1) * BK; }
        else if (NSEG > 1 && t >= T0) { s = 1; k0 = (t - T0) * BK; }
        else                          { s = 0; k0 = t * BK; }
    };
    auto issueA = [&](int t) {
        int s, k0; map_tile(t, s, k0);
        const float* p = abase[s] + k0;
        #pragma unroll
        for (int q = 0; q < 4; q++) af[q] = *(const float4*)(p + q * 4);
    };
    auto storeA = [&](int t, int buf) {
        int s, k0; map_tile(t, s, k0);
        const int rl = segs[s].relu;
        float* dst = As + buf * (BK * ASTR);
        #pragma unroll
        for (int q = 0; q < 4; q++) {
            float4 v = af[q];
            if (rl) {
                v.x = fmaxf(v.x, 0.f); v.y = fmaxf(v.y, 0.f);
                v.z = fmaxf(v.z, 0.f); v.w = fmaxf(v.w, 0.f);
            }
            int kk = ar_half * 16 + q * 4;
            dst[(kk + 0) * ASTR + ar_row] = v.x;
            dst[(kk + 1) * ASTR + ar_row] = v.y;
            dst[(kk + 2) * ASTR + ar_row] = v.z;
            dst[(kk + 3) * ASTR + ar_row] = v.w;
        }
    };
    auto issueW = [&](int t, int buf) {
        int s, k0; map_tile(t, s, k0);
        const float* wp = segs[s].W + (size_t)k0 * BN;
        uint32_t sa = (uint32_t)__cvta_generic_to_shared(Wsm + buf * (BK * BN));
        #pragma unroll
        for (int ps = 0; ps < WPASS; ps++) {
            int i = tid * 4 + ps * 1024;
            cp16(sa + i * 4, wp + i);
        }
    };

    unsigned long long acc2[4][8];
    #pragma unroll
    for (int p = 0; p < 4; p++)
        #pragma unroll
        for (int j = 0; j < 8; j++) acc2[p][j] = 0ull;

    issueA(ts); storeA(ts, 0); issueW(ts, 0); cp_commit();
    if (ts + 1 < te) issueA(ts + 1);
    cp_wait0();
    __syncthreads();

    for (int t = ts; t < te; t++) {
        int buf = (t - ts) & 1;
        if (t + 1 < te) { issueW(t + 1, buf ^ 1); cp_commit(); storeA(t + 1, buf ^ 1); }
        if (t + 2 < te) issueA(t + 2);

        const float* as = As  + buf * (BK * ASTR);
        const float* ws = Wsm + buf * (BK * BN);
        #pragma unroll
        for (int k = 0; k < BK; k++) {
            ulonglong2 alo = *(const ulonglong2*)(as + k * ASTR + ty * 4);
            ulonglong2 ahi = *(const ulonglong2*)(as + k * ASTR + BM / 2 + ty * 4);
            float4 wlo = *(const float4*)(ws + k * BN + tx * 4);
            float4 whi = *(const float4*)(ws + k * BN + BN / 2 + tx * 4);
            unsigned long long ar[4] = {alo.x, alo.y, ahi.x, ahi.y};
            unsigned long long bd[8] = {
                pack2(wlo.x), pack2(wlo.y), pack2(wlo.z), pack2(wlo.w),
                pack2(whi.x), pack2(whi.y), pack2(whi.z), pack2(whi.w)};
            #pragma unroll
            for (int p = 0; p < 4; p++)
                #pragma unroll
                for (int j = 0; j < 8; j++)
                    ffma2(acc2[p][j], ar[p], bd[j]);
        }
        cp_wait0();
        __syncthreads();
    }

    float bv[8];
    if (OUT == 1) {
        #pragma unroll
        for (int j = 0; j < 4; j++) {
            bv[j]     = bias ? bias[tx * 4 + j] : 0.f;
            bv[4 + j] = bias ? bias[BN / 2 + tx * 4 + j] : 0.f;
        }
    }
    #pragma unroll
    for (int h = 0; h < 8; h++) {
        int hh = h & 3;
        int p  = ((h >> 2) << 1) | (hh >> 1);
        int c  = hh & 1;
        int rl = (h < 4) ? (ty * 4 + hh) : (BM / 2 + ty * 4 + hh);
        if (row0 + rl < M) {
            float* op = out + (size_t)sidx[rl] * BN;
            if (OUT == 2) {
                float v0 = sel2(acc2[p][0], c), v1 = sel2(acc2[p][1], c);
                float v2 = sel2(acc2[p][2], c), v3 = sel2(acc2[p][3], c);
                asm volatile("red.global.add.v4.f32 [%0], {%1,%2,%3,%4};"
                             :: "l"(op + tx * 4), "f"(v0), "f"(v1), "f"(v2), "f"(v3)
                             : "memory");
                float u0 = sel2(acc2[p][4], c), u1 = sel2(acc2[p][5], c);
                float u2 = sel2(acc2[p][6], c), u3 = sel2(acc2[p][7], c);
                asm volatile("red.global.add.v4.f32 [%0], {%1,%2,%3,%4};"
                             :: "l"(op + BN / 2 + tx * 4), "f"(u0), "f"(u1), "f"(u2), "f"(u3)
                             : "memory");
            } else {
                float4 o0, o1;
                o0.x = sel2(acc2[p][0], c) + bv[0];
                o0.y = sel2(acc2[p][1], c) + bv[1];
                o0.z = sel2(acc2[p][2], c) + bv[2];
                o0.w = sel2(acc2[p][3], c) + bv[3];
                o1.x = sel2(acc2[p][4], c) + bv[4];
                o1.y = sel2(acc2[p][5], c) + bv[5];
                o1.z = sel2(acc2[p][6], c) + bv[6];
                o1.w = sel2(acc2[p][7], c) + bv[7];
                if (relu_out) {
                    o0.x = fmaxf(o0.x, 0.f); o0.y = fmaxf(o0.y, 0.f);
                    o0.z = fmaxf(o0.z, 0.f); o0.w = fmaxf(o0.w, 0.f);
                    o1.x = fmaxf(o1.x, 0.f); o1.y = fmaxf(o1.y, 0.f);
                    o1.z = fmaxf(o1.z, 0.f); o1.w = fmaxf(o1.w, 0.f);
                }
                *(float4*)(op + tx * 4) = o0;
                *(float4*)(op + BN / 2 + tx * 4) = o1;
            }
        }
    }
}

// ---------------- layer-3 master kernels ----------------

__global__ __launch_bounds__(256) void master_node_kernel(
    const float* __restrict__ x2, const float* __restrict__ ws3,
    const float* __restrict__ bs3, float* __restrict__ out)
{
    int g = blockIdx.x;
    int c = threadIdx.x;
    const float* xr = x2 + (size_t)g * NODES_PER_GRAPH * 128;
    float acc = bs3[c];
    #pragma unroll 8
    for (int k = 0; k < 128; k++)
        acc += fmaxf(xr[k], 0.f) * ws3[(size_t)k * 256 + c];
    out[(size_t)g * 256 + c] = acc;
}

// out[g] += relu_x2[src]@wmx3 + e2@wme3 over list3 positions (warp per edge)
__global__ __launch_bounds__(256) void master_edge3_kernel(
    const float* __restrict__ x2,
    const int* __restrict__ src, const int* __restrict__ dst,
    const float* __restrict__ wmx3, const float* __restrict__ wme3,
    float* __restrict__ out)
{
    int cnt = d_cnt[2];
    int lane = threadIdx.x & 31;
    for (int i = blockIdx.x * 8 + (threadIdx.x >> 5); i < cnt; i += gridDim.x * 8) {
        int e  = d_list3[i];
        int sh = src[e];
        int g  = dst[e] / NODES_PER_GRAPH;
        float acc[8];
        #pragma unroll
        for (int j = 0; j < 8; j++) acc[j] = 0.f;
        const float* xr = x2 + (size_t)sh * 128;
        for (int k = 0; k < 128; k++) {
            float a = fmaxf(xr[k], 0.f);
            const float* wr = wmx3 + (size_t)k * 256;
            #pragma unroll
            for (int j = 0; j < 8; j++) acc[j] += a * wr[lane + j * 32];
        }
        const float* er = g_e2c + (size_t)i * 64;
        for (int k = 0; k < 64; k++) {
            float a = er[k];
            const float* wr = wme3 + (size_t)k * 256;
            #pragma unroll
            for (int j = 0; j < 8; j++) acc[j] += a * wr[lane + j * 32];
        }
        float* op = out + (size_t)g * 256;
        #pragma unroll
        for (int j = 0; j < 8; j++) atomicAdd(op + lane + j * 32, acc[j]);
    }
}

template<int BM, int BN, int BK, int NSEG>
static int smem_bytes() {
    constexpr int ASTR = BM + 4;
    return (2 * BK * ASTR + 2 * BK * BN) * 4 + NSEG * BM * 4 + BM * 4;
}

extern "C" void kernel_launch(void* const* d_in, const int* in_sizes, int n_in,
                              void* d_out, int out_size)
{
    const float* x         = (const float*)d_in[0];
    const int*   edge_idx  = (const int*)d_in[1];
    const float* edge_attr = (const float*)d_in[2];
    const float* w_proj    = (const float*)d_in[4];
    const float* b_proj    = (const float*)d_in[5];
    const float* P[30];
    for (int i = 0; i < 30 && i < n_in; i++) P[i] = (const float*)d_in[i];

    const int* src = edge_idx;
    const int* dst = edge_idx + N_EDGES;
    float* out = (float*)d_out;

    void* p;
    cudaGetSymbolAddress(&p, g_x1);     float* x1_p    = (float*)p;
    cudaGetSymbolAddress(&p, g_x2);     float* x2_p    = (float*)p;
    cudaGetSymbolAddress(&p, g_aggx);   float* aggx_p  = (float*)p;
    cudaGetSymbolAddress(&p, g_agga);   float* agga_p  = (float*)p;
    cudaGetSymbolAddress(&p, g_aggx2);  float* aggx2_p = (float*)p;
    cudaGetSymbolAddress(&p, g_agge1);  float* agge1_p = (float*)p;
    cudaGetSymbolAddress(&p, g_ec);     float* ec_p    = (float*)p;
    cudaGetSymbolAddress(&p, g_e1c);    float* e1c_p   = (float*)p;
    cudaGetSymbolAddress(&p, g_e2c);    float* e2c_p   = (float*)p;
    cudaGetSymbolAddress(&p, g_wpm);    float* wpm_p   = (float*)p;
    cudaGetSymbolAddress(&p, d_list2);  const int* l2  = (const int*)p;
    cudaGetSymbolAddress(&p, d_list3);  const int* l3  = (const int*)p;
    cudaGetSymbolAddress(&p, d_pos2);   const int* pos2 = (const int*)p;
    cudaGetSymbolAddress(&p, d_nlist1); const int* n1  = (const int*)p;
    cudaGetSymbolAddress(&p, d_nlist2); const int* n2  = (const int*)p;
    cudaGetSymbolAddress(&p, d_cnt);    const int* cnt = (const int*)p;
    const int* c_n2 = cnt + 0;
    const int* c_l2 = cnt + 1;
    const int* c_l3 = cnt + 2;
    const int* c_n1 = cnt + 3;

    static cudaStream_t sB = nullptr, sC = nullptr, sD = nullptr;
    static cudaEvent_t evRoot, evCW, evMark, evCSR, evL2, evSeed, evG1,
                       evS2, evE1, evX1, evE2;
    if (!sB) {
        cudaFuncSetAttribute(gemm_kernel<256, 64, 16, 1, 1>,
            cudaFuncAttributeMaxDynamicSharedMemorySize, smem_bytes<256, 64, 16, 1>());
        cudaFuncSetAttribute(gemm_kernel<256, 64, 16, 3, 1>,
            cudaFuncAttributeMaxDynamicSharedMemorySize, smem_bytes<256, 64, 16, 3>());
        cudaFuncSetAttribute(gemm_kernel<128, 128, 32, 1, 2>,
            cudaFuncAttributeMaxDynamicSharedMemorySize, smem_bytes<128, 128, 32, 1>());
        cudaFuncSetAttribute(gemm_kernel<128, 128, 32, 2, 2>,
            cudaFuncAttributeMaxDynamicSharedMemorySize, smem_bytes<128, 128, 32, 2>());
        cudaFuncSetAttribute(gemm_kernel<128, 128, 32, 3, 2>,
            cudaFuncAttributeMaxDynamicSharedMemorySize, smem_bytes<128, 128, 32, 3>());
        cudaStreamCreateWithFlags(&sB, cudaStreamNonBlocking);
        cudaStreamCreateWithFlags(&sC, cudaStreamNonBlocking);
        cudaStreamCreateWithFlags(&sD, cudaStreamNonBlocking);
        cudaEventCreateWithFlags(&evRoot, cudaEventDisableTiming);
        cudaEventCreateWithFlags(&evCW,   cudaEventDisableTiming);
        cudaEventCreateWithFlags(&evMark, cudaEventDisableTiming);
        cudaEventCreateWithFlags(&evCSR,  cudaEventDisableTiming);
        cudaEventCreateWithFlags(&evL2,   cudaEventDisableTiming);
        cudaEventCreateWithFlags(&evSeed, cudaEventDisableTiming);
        cudaEventCreateWithFlags(&evG1,   cudaEventDisableTiming);
        cudaEventCreateWithFlags(&evS2,   cudaEventDisableTiming);
        cudaEventCreateWithFlags(&evE1,   cudaEventDisableTiming);
        cudaEventCreateWithFlags(&evX1,   cudaEventDisableTiming);
        cudaEventCreateWithFlags(&evE2,   cudaEventDisableTiming);
    }

    Seg z = {nullptr, nullptr, nullptr, 0, 0};

    // ---- fork root: stream C does combine_w concurrently with marking ----
    cudaEventRecord(evRoot, 0);
    cudaStreamWaitEvent(sC, evRoot, 0);
    combine_w_kernel<<<129, 128, 0, sC>>>(w_proj, b_proj, P[9]);   // P[9]=wme1
    cudaEventRecord(evCW, sC);

    // ---- chain A: marking (+ fused degree count + nlist1/2 seed) ----
    zero_kernel<<<256, 256>>>();
    mark2_count_scan<<<1024, 256>>>(src, dst);
    cudaEventRecord(evMark, 0);

    // ---- stream D: CSR build (concurrent with list2_scan on A) ----
    cudaStreamWaitEvent(sD, evMark, 0);
    scanA_kernel<<<SCAN_NB, SCAN_B, 0, sD>>>();
    scanB_kernel<<<SCAN_NB, SCAN_B, 0, sD>>>();
    scatter_csr_kernel<<<1024, 256, 0, sD>>>(dst);
    cudaEventRecord(evCSR, sD);

    // ---- stream C: seed2 (needs nlist2) ----
    cudaStreamWaitEvent(sC, evMark, 0);
    seed2_kernel<<<256, 256, 0, sC>>>(x2_p, P[15]);
    cudaEventRecord(evS2, sC);

    // ---- chain A: list2 (full-edge scan; completes nlist1) ----
    list2_scan<<<1024, 256>>>(src, dst);
    cudaEventRecord(evL2, 0);

    // ---- stream D: seed x1 then G1 = x@ws1 (red-add), overlaps agg1 ----
    cudaStreamWaitEvent(sD, evL2, 0);
    cudaStreamWaitEvent(sD, evCW, 0);
    seed_x1_kernel<<<512, 256, 0, sD>>>(x1_p, P[7]);
    cudaEventRecord(evSeed, sD);
    {
        Seg a = {x, nullptr, P[6], 256, 0};
        gemm_kernel<128, 128, 32, 1, 2>
            <<<dim3(CAP_N1 / 128, 1), 256, smem_bytes<128, 128, 32, 1>(), sD>>>(
            a, z, z, nullptr, 0, x1_p, n1, nullptr, c_n1);
    }
    cudaEventRecord(evG1, sD);

    // ---- chain B: e0 -> e1 (single-pass, fused bias+relu) ----
    cudaStreamWaitEvent(sB, evL2, 0);
    {
        Seg a = {edge_attr, nullptr, w_proj, 128, 0};
        gemm_kernel<256, 64, 16, 1, 1>
            <<<CAP_L2 / 256, 256, smem_bytes<256, 64, 16, 1>(), sB>>>(
            a, z, z, b_proj, 0, ec_p, l2, POS_GATHER, c_l2);
    }
    {
        Seg a = {x,    src,        P[10], 256, 0};
        Seg b = {x,    dst,        P[11], 256, 0};
        Seg c = {ec_p, POS_GATHER, P[12], 64,  0};
        gemm_kernel<256, 64, 16, 3, 1>
            <<<CAP_L2 / 256, 256, smem_bytes<256, 64, 16, 3>(), sB>>>(
            a, b, c, P[13], 1, e1c_p, l2, POS_GATHER, c_l2);
    }
    cudaEventRecord(evE1, sB);

    // ---- chain A: CSR aggregation + G2 (x1 stays pre-relu in memory) ----
    cudaStreamWaitEvent(0, evCSR, 0);
    agg1_csr_kernel<<<2048, 256>>>(x, edge_attr, src);
    cudaStreamWaitEvent(0, evSeed, 0);
    {
        Seg a = {aggx_p, nullptr, P[8],  256, 0};
        Seg b = {agga_p, nullptr, wpm_p, 128, 0};
        gemm_kernel<128, 128, 32, 2, 2>
            <<<dim3(CAP_N1 / 128, 2), 256, smem_bytes<128, 128, 32, 2>()>>>(
            a, b, z, nullptr, 0, x1_p, n1, nullptr, c_n1);
    }
    cudaStreamWaitEvent(0, evG1, 0);
    cudaEventRecord(evX1, 0);                    // x1 final (pre-relu)

    // ---- chain B: e2 (relu(x1) on load; single-pass bias+relu) ----
    cudaStreamWaitEvent(sB, evX1, 0);
    {
        Seg a = {x1_p,  src,   P[18], 128, 1};
        Seg b = {x1_p,  dst,   P[19], 128, 1};
        Seg c = {e1c_p, pos2,  P[20], 64,  0};
        gemm_kernel<256, 64, 16, 3, 1>
            <<<CAP_L3 / 256, 256, smem_bytes<256, 64, 16, 3>(), sB>>>(
            a, b, c, P[21], 1, e2c_p, l3, POS_GATHER, c_l3);
    }
    cudaEventRecord(evE2, sB);

    // ---- chain A: layer 2 + masters ----
    cudaStreamWaitEvent(0, evE1, 0);
    cudaStreamWaitEvent(0, evS2, 0);
    agg2_kernel<<<512, 256>>>(x1_p, src, dst);   // relu applied inline
    {
        Seg a = {x1_p,    nullptr, P[14], 128, 1};
        Seg b = {aggx2_p, nullptr, P[16], 128, 0};
        Seg c = {agge1_p, nullptr, P[17], 64,  0};
        gemm_kernel<128, 128, 32, 3, 2>
            <<<dim3(CAP_N2 / 128, 4), 256, smem_bytes<128, 128, 32, 3>()>>>(
            a, b, c, nullptr, 0, x2_p, n2, nullptr, c_n2);
    }
    master_node_kernel<<<N_GRAPHS, 256>>>(x2_p, P[22], P[23], out);
    cudaStreamWaitEvent(0, evE2, 0);
    master_edge3_kernel<<<128, 256>>>(x2_p, src, dst, P[24], P[25], out);
}

// round 15
// speedup vs baseline: 1.2098x; 1.1400x over previous
#include <cuda_runtime.h>
#include <cstddef>
#include <cstdint>

#define N_NODES 50000
#define N_EDGES 800000
#define N_GRAPHS 50
#define NODES_PER_GRAPH 1000

#define CAP_L2 32768      // edges into flag2 nodes (expected ~13.4K)
#define CAP_L3 4096       // master-destination edges (expected ~800)
#define CAP_N1 24576      // nodes needing x1 (expected ~14.2K)
#define CAP_N2 4096       // nodes needing x2 (expected ~850)

#define POS_GATHER ((const int*)(size_t)1)   // sentinel: use list position as row

#define SCAN_B 256
#define SCAN_NB ((N_NODES + SCAN_B - 1) / SCAN_B)   // 196

// Scratch (device globals; allocation rules forbid cudaMalloc)
__device__ float g_x1[(size_t)N_NODES * 128];
__device__ float g_x2[(size_t)N_NODES * 128];
__device__ float g_aggx[(size_t)N_NODES * 256];    // sum x[src] per dst (layer 1)
__device__ float g_agga[(size_t)N_NODES * 128];    // sum edge_attr per dst (layer 1)
__device__ float g_aggx2[(size_t)N_NODES * 128];   // sum relu_x1[src] per dst (layer 2)
__device__ float g_agge1[(size_t)N_NODES * 64];    // sum e1 per dst (layer 2)
__device__ float g_ec[(size_t)CAP_L2 * 64];        // e0 rows, list2-position indexed
__device__ float g_e1c[(size_t)CAP_L2 * 64];       // e1 rows, list2-position indexed
__device__ float g_e2c[(size_t)CAP_L3 * 64];       // e2 rows, list3-position indexed
__device__ float g_wpm[128 * 128];                 // w_proj @ wme1
__device__ float g_bpm[128];                       // b_proj @ wme1

__device__ int d_flag1[N_NODES];
__device__ int d_flag2[N_NODES];
__device__ int d_deg[N_NODES];     // FULL in-degree of every node
__device__ int d_off[N_NODES];     // CSR exclusive offsets
__device__ int d_cur[N_NODES];     // scatter cursors
__device__ int d_csr[N_EDGES];     // edge ids grouped by dst
__device__ int d_bsum[SCAN_NB];    // per-block sums for scan
__device__ int d_list2[CAP_L2];
__device__ int d_list3[CAP_L3];
__device__ int d_pos2[N_EDGES];    // edge id -> list2 position (valid for list2 edges)
__device__ int d_nlist1[N_NODES];
__device__ int d_nlist2[CAP_N2];
__device__ int d_cnt[8];           // 0:n2 1:l2 2:l3 3:n1

struct Seg {
    const float* base;    // row-major [*, K]
    const int*   gather;  // applied to rowlist value; nullptr = value; POS_GATHER = position
    const float* W;       // [K, BN] row-major
    int K;
};

__device__ __forceinline__ unsigned long long pack2(float v) {
    unsigned long long r;
    asm("mov.b64 %0, {%1, %1};" : "=l"(r) : "f"(v));
    return r;
}
__device__ __forceinline__ void ffma2(unsigned long long& d,
                                      unsigned long long a,
                                      unsigned long long b) {
    asm("fma.rn.f32x2 %0, %1, %2, %0;" : "+l"(d) : "l"(a), "l"(b));
}
__device__ __forceinline__ float sel2(unsigned long long v, int hi) {
    float2 f = *(float2*)&v; return hi ? f.y : f.x;
}
__device__ __forceinline__ void cp16(uint32_t saddr, const float* g) {
    asm volatile("cp.async.cg.shared.global [%0], [%1], 16;" :: "r"(saddr), "l"(g));
}
__device__ __forceinline__ void cp_commit() {
    asm volatile("cp.async.commit_group;" ::: "memory");
}
__device__ __forceinline__ void cp_wait0() {
    asm volatile("cp.async.wait_group 0;" ::: "memory");
}
__device__ __forceinline__ void redv4(float* p, float4 v) {
    asm volatile("red.global.add.v4.f32 [%0], {%1,%2,%3,%4};"
                 :: "l"(p), "f"(v.x), "f"(v.y), "f"(v.z), "f"(v.w) : "memory");
}

// ---------------- frontier marking / CSR build ----------------

__global__ __launch_bounds__(256) void zero_kernel()
{
    int n4 = N_NODES / 4;
    int4 z = {0, 0, 0, 0};
    for (int i = blockIdx.x * 256 + threadIdx.x; i < n4; i += gridDim.x * 256) {
        ((int4*)d_flag1)[i] = z;
        ((int4*)d_flag2)[i] = z;
        ((int4*)d_deg)[i]   = z;
    }
    if (blockIdx.x == 0 && threadIdx.x < 8) d_cnt[threadIdx.x] = 0;
}

// fused: in-degree count (ALL nodes) + master-edge marking
// flag2/nlist2 dedup via atomicExch; master edges -> list3; flag1 |= flag2
__global__ __launch_bounds__(256) void mark2_count_scan(
    const int* __restrict__ src, const int* __restrict__ dst)
{
    int n4 = N_EDGES / 4;
    for (int i = blockIdx.x * 256 + threadIdx.x; i < n4; i += gridDim.x * 256) {
        int4 d = ((const int4*)dst)[i];
        int e = i * 4;
        #pragma unroll
        for (int q = 0; q < 4; q++) {
            int dd = (q == 0) ? d.x : (q == 1) ? d.y : (q == 2) ? d.z : d.w;
            atomicAdd(&d_deg[dd], 1);
            if (dd % NODES_PER_GRAPH == 0) {
                int s = src[e + q];
                if (atomicExch(&d_flag2[s], 1) == 0) {
                    d_flag1[s] = 1;
                    d_nlist2[atomicAdd(&d_cnt[0], 1)] = s;
                }
                d_list3[atomicAdd(&d_cnt[2], 1)] = e + q;
            }
        }
    }
    if (blockIdx.x == 0 && threadIdx.x < N_GRAPHS) {
        int v = threadIdx.x * NODES_PER_GRAPH;
        if (atomicExch(&d_flag2[v], 1) == 0) {
            d_flag1[v] = 1;
            d_nlist2[atomicAdd(&d_cnt[0], 1)] = v;
        }
    }
}

// edges into flag2 nodes -> list2 (+pos map); their srcs need x1
__global__ __launch_bounds__(256) void list2_scan(
    const int* __restrict__ src, const int* __restrict__ dst)
{
    int n4 = N_EDGES / 4;
    for (int i = blockIdx.x * 256 + threadIdx.x; i < n4; i += gridDim.x * 256) {
        int4 d = ((const int4*)dst)[i];
        int e = i * 4;
        #pragma unroll
        for (int q = 0; q < 4; q++) {
            int dd = (q == 0) ? d.x : (q == 1) ? d.y : (q == 2) ? d.z : d.w;
            int ee = e + q;
            if (d_flag2[dd]) {
                int j = atomicAdd(&d_cnt[1], 1);
                d_list2[j] = ee;
                d_pos2[ee] = j;
                d_flag1[src[ee]] = 1;
            }
        }
    }
}

// node-id-ordered compaction of flag1 -> nlist1 (order preserves CSR locality)
__global__ __launch_bounds__(256) void nodes1_kernel()
{
    int v = blockIdx.x * 256 + threadIdx.x;
    if (v < N_NODES && d_flag1[v]) {
        int i = atomicAdd(&d_cnt[3], 1);
        d_nlist1[i] = v;
    }
}

// ---- coalesced exclusive scan of d_deg -> d_off / d_cur ----

__device__ __forceinline__ int block_exscan(int v, int* wsh)
{
    int lane = threadIdx.x & 31, w = threadIdx.x >> 5;
    int s = v;
    #pragma unroll
    for (int o = 1; o < 32; o <<= 1) {
        int n = __shfl_up_sync(0xffffffffu, s, o);
        if (lane >= o) s += n;
    }
    if (lane == 31) wsh[w] = s;
    __syncthreads();
    if (w == 0 && lane < 8) {
        int v8 = wsh[lane];
        #pragma unroll
        for (int o = 1; o < 8; o <<= 1) {
            int n = __shfl_up_sync(0xffu, v8, o);
            if (lane >= o) v8 += n;
        }
        wsh[lane] = v8;
    }
    __syncthreads();
    return s - v + (w ? wsh[w - 1] : 0);
}

__global__ __launch_bounds__(SCAN_B) void scanA_kernel()
{
    __shared__ int sh[SCAN_B];
    int idx = blockIdx.x * SCAN_B + threadIdx.x;
    sh[threadIdx.x] = (idx < N_NODES) ? d_deg[idx] : 0;
    __syncthreads();
    for (int o = 128; o > 0; o >>= 1) {
        if (threadIdx.x < o) sh[threadIdx.x] += sh[threadIdx.x + o];
        __syncthreads();
    }
    if (threadIdx.x == 0) d_bsum[blockIdx.x] = sh[0];
}

// merged: per-block offset (sum of bsum[0..b)) + block exclusive scan
__global__ __launch_bounds__(SCAN_B) void scanB_kernel()
{
    __shared__ int wsh[8];
    __shared__ int boff_sh;
    int partial = 0;
    for (int i = threadIdx.x; i < blockIdx.x; i += SCAN_B)
        partial += d_bsum[i];
    #pragma unroll
    for (int o = 16; o > 0; o >>= 1)
        partial += __shfl_down_sync(0xffffffffu, partial, o);
    if ((threadIdx.x & 31) == 0) wsh[threadIdx.x >> 5] = partial;
    __syncthreads();
    if (threadIdx.x == 0) {
        int s = 0;
        #pragma unroll
        for (int w = 0; w < 8; w++) s += wsh[w];
        boff_sh = s;
    }
    __syncthreads();
    int boff = boff_sh;
    int idx = blockIdx.x * SCAN_B + threadIdx.x;
    int v = (idx < N_NODES) ? d_deg[idx] : 0;
    int excl = block_exscan(v, wsh) + boff;
    if (idx < N_NODES) { d_off[idx] = excl; d_cur[idx] = excl; }
}

// scatter all edges into CSR buckets by dst
__global__ __launch_bounds__(256) void scatter_csr_kernel(const int* __restrict__ dst)
{
    int n4 = N_EDGES / 4;
    for (int i = blockIdx.x * 256 + threadIdx.x; i < n4; i += gridDim.x * 256) {
        int4 d = ((const int4*)dst)[i];
        int e = i * 4;
        d_csr[atomicAdd(&d_cur[d.x], 1)] = e + 0;
        d_csr[atomicAdd(&d_cur[d.y], 1)] = e + 1;
        d_csr[atomicAdd(&d_cur[d.z], 1)] = e + 2;
        d_csr[atomicAdd(&d_cur[d.w], 1)] = e + 3;
    }
}

// W' = w_proj @ wme1 (128x128); bvec = b_proj @ wme1 (128)
__global__ __launch_bounds__(128) void combine_w_kernel(
    const float* __restrict__ w_proj, const float* __restrict__ b_proj,
    const float* __restrict__ wme1)
{
    int n = threadIdx.x;
    int k = blockIdx.x;
    float s = 0.f;
    if (k < 128) {
        for (int j = 0; j < 64; j++)
            s += w_proj[k * 64 + j] * wme1[j * 128 + n];
        g_wpm[k * 128 + n] = s;
    } else {
        for (int j = 0; j < 64; j++)
            s += b_proj[j] * wme1[j * 128 + n];
        g_bpm[n] = s;
    }
}

// layer-1 aggregation via CSR: warp per flagged node, register accumulation
__global__ __launch_bounds__(256) void agg1_csr_kernel(
    const float* __restrict__ x, const float* __restrict__ eattr,
    const int* __restrict__ src)
{
    int n = d_cnt[3];
    int lane = threadIdx.x & 31;
    for (int i = blockIdx.x * 8 + (threadIdx.x >> 5); i < n; i += gridDim.x * 8) {
        int v   = d_nlist1[i];
        int beg = d_off[v];
        int end = beg + d_deg[v];
        float4 a0 = {0.f, 0.f, 0.f, 0.f}, a1 = a0, aa = a0;
        for (int j = beg; j < end; j++) {
            int e = d_csr[j];
            int s = src[e];
            const float4* xr = (const float4*)(x + (size_t)s * 256);
            float4 u0 = xr[lane];
            float4 u1 = xr[lane + 32];
            a0.x += u0.x; a0.y += u0.y; a0.z += u0.z; a0.w += u0.w;
            a1.x += u1.x; a1.y += u1.y; a1.z += u1.z; a1.w += u1.w;
            float4 w = ((const float4*)(eattr + (size_t)e * 128))[lane];
            aa.x += w.x; aa.y += w.y; aa.z += w.z; aa.w += w.w;
        }
        ((float4*)(g_aggx + (size_t)v * 256))[lane]      = a0;
        ((float4*)(g_aggx + (size_t)v * 256))[lane + 32] = a1;
        ((float4*)(g_agga + (size_t)v * 128))[lane]      = aa;
    }
}

// x1[v] = bs1 + deg[v] * bvec for nlist1 nodes
__global__ __launch_bounds__(256) void seed_x1_kernel(
    float* __restrict__ x1, const float* __restrict__ bs1)
{
    int n = d_cnt[3];
    int total = n * 32;
    for (int i = blockIdx.x * 256 + threadIdx.x; i < total; i += gridDim.x * 256) {
        int r = i >> 5, c = i & 31;
        int v = d_nlist1[r];
        float dg = (float)d_deg[v];
        float4 b = ((const float4*)bs1)[c];
        float4 pv = ((const float4*)g_bpm)[c];
        float4 o = {b.x + dg * pv.x, b.y + dg * pv.y,
                    b.z + dg * pv.z, b.w + dg * pv.w};
        ((float4*)(x1 + (size_t)v * 128))[c] = o;
    }
}

// relu x1 rows in nlist1
__global__ __launch_bounds__(256) void relu_rows_kernel(float* __restrict__ x1)
{
    int n = d_cnt[3];
    int total = n * 32;
    for (int i = blockIdx.x * 256 + threadIdx.x; i < total; i += gridDim.x * 256) {
        int r = i >> 5, c = i & 31;
        float4* p = (float4*)(x1 + (size_t)d_nlist1[r] * 128) + c;
        float4 v = *p;
        v.x = fmaxf(v.x, 0.f); v.y = fmaxf(v.y, 0.f);
        v.z = fmaxf(v.z, 0.f); v.w = fmaxf(v.w, 0.f);
        *p = v;
    }
}

// seed compact 64-wide rows [0,cnt) with bias
__global__ __launch_bounds__(256) void seed_rows64_kernel(
    float* __restrict__ buf, const float* __restrict__ bias, const int* __restrict__ cntp)
{
    int total = *cntp * 16;
    for (int i = blockIdx.x * 256 + threadIdx.x; i < total; i += gridDim.x * 256)
        ((float4*)buf)[i] = ((const float4*)bias)[i & 15];
}

// relu compact 64-wide rows [0,cnt)
__global__ __launch_bounds__(256) void relu_rows64_kernel(
    float* __restrict__ buf, const int* __restrict__ cntp)
{
    int total = *cntp * 16;
    for (int i = blockIdx.x * 256 + threadIdx.x; i < total; i += gridDim.x * 256) {
        float4 v = ((float4*)buf)[i];
        v.x = fmaxf(v.x, 0.f); v.y = fmaxf(v.y, 0.f);
        v.z = fmaxf(v.z, 0.f); v.w = fmaxf(v.w, 0.f);
        ((float4*)buf)[i] = v;
    }
}

// zero aggx2/agge1 and seed x2 = bs2 for nlist2 nodes
__global__ __launch_bounds__(256) void seed2_kernel(
    float* __restrict__ x2, const float* __restrict__ bs2)
{
    int n = d_cnt[0];
    int total = n * 80;
    float4 z = {0.f, 0.f, 0.f, 0.f};
    for (int i = blockIdx.x * 256 + threadIdx.x; i < total; i += gridDim.x * 256) {
        int r = i / 80, q = i % 80;
        int v = d_nlist2[r];
        if (q < 32)      ((float4*)(g_aggx2 + (size_t)v * 128))[q] = z;
        else if (q < 48) ((float4*)(g_agge1 + (size_t)v * 64))[q - 32] = z;
        else ((float4*)(x2 + (size_t)v * 128))[q - 48] = ((const float4*)bs2)[q - 48];
    }
}

// layer-2 aggregation over list2 positions: red-add relu_x1[src], e1 (compact)
__global__ __launch_bounds__(256) void agg2_kernel(
    const float* __restrict__ x1,
    const int* __restrict__ src, const int* __restrict__ dst)
{
    int cnt = d_cnt[1];
    int lane = threadIdx.x & 31;
    for (int i = blockIdx.x * 8 + (threadIdx.x >> 5); i < cnt; i += gridDim.x * 8) {
        int e  = d_list2[i];
        int sh = src[e];
        int dh = dst[e];
        float4 v = ((const float4*)(x1 + (size_t)sh * 128))[lane];
        redv4(g_aggx2 + (size_t)dh * 128 + lane * 4, v);
        if (lane < 16) {
            float4 u = ((const float4*)(g_e1c + (size_t)i * 64))[lane];
            redv4(g_agge1 + (size_t)dh * 64 + lane * 4, u);
        }
    }
}

// ---------------- pipelined gather-GEMM (f32x2 FMA, 8x8 thread tile) ----------------
template<int BM, int BN, int BK, int NSEG, int OUT>
__global__ __launch_bounds__(256, 2) void gemm_kernel(
    Seg s0, Seg s1, Seg s2,
    const float* __restrict__ bias, int relu_out,
    float* __restrict__ out,
    const int* __restrict__ rowlist,
    const int* __restrict__ scat_map,
    const int* __restrict__ Mptr)
{
    constexpr int ASTR  = BM + 4;
    constexpr int WCOL  = BN / 64;
    constexpr int WPASS = (BK * BN) / 1024;

    const int M    = *Mptr;
    const int row0 = blockIdx.x * BM;
    if (row0 >= M) return;

    extern __shared__ float smem[];
    float* As   = smem;
    float* Wsm  = smem + 2 * BK * ASTR;
    int*   ridx = (int*)(Wsm + 2 * BK * BN);
    int*   sidx = ridx + NSEG * BM;

    Seg segs[3] = {s0, s1, s2};

    const int tid  = threadIdx.x;
    const int warp = tid >> 5;
    const int lane = tid & 31;

    const int wc = warp % WCOL;
    const int wr = warp / WCOL;
    const int ty = wr * 4 + (lane >> 3);
    const int tx = wc * 8 + (lane & 7);

    for (int i = tid; i < BM; i += 256) {
        int r = row0 + i;
        int rc = (r < M) ? r : row0;
        int rid = rowlist[rc];
        #pragma unroll
        for (int s = 0; s < NSEG; s++) {
            const int* g = segs[s].gather;
            ridx[s * BM + i] = (g == POS_GATHER) ? rc : (g ? g[rid] : rid);
        }
        sidx[i] = (scat_map == POS_GATHER) ? rc : (scat_map ? scat_map[rid] : rid);
    }
    __syncthreads();

    const int T0 = segs[0].K / BK;
    const int T1 = T0 + ((NSEG > 1) ? segs[1].K / BK : 0);
    const int T  = T1 + ((NSEG > 2) ? segs[2].K / BK : 0);
    const int ts = T * blockIdx.y / gridDim.y;
    const int te = T * (blockIdx.y + 1) / gridDim.y;

    const int ar_row  = (BM == 256) ? tid : (tid & (BM - 1));
    const int ar_half = (BM == 256) ? 0 : (tid >> 7);

    const float* abase[3];
    #pragma unroll
    for (int s = 0; s < NSEG; s++)
        abase[s] = segs[s].base + (size_t)ridx[s * BM + ar_row] * segs[s].K
                   + ar_half * 16;

    float4 af[4];

    auto map_tile = [&](int t, int& s, int& k0) {
        if (NSEG > 2 && t >= T1)      { s = 2; k0 = (t - T1) * BK; }
        else if (NSEG > 1 && t >= T0) { s = 1; k0 = (t - T0) * BK; }
        else                          { s = 0; k0 = t * BK; }
    };
    auto issueA = [&](int t) {
        int s, k0; map_tile(t, s, k0);
        const float* p = abase[s] + k0;
        #pragma unroll
        for (int q = 0; q < 4; q++) af[q] = *(const float4*)(p + q * 4);
    };
    auto storeA = [&](int buf) {
        float* dst = As + buf * (BK * ASTR);
        #pragma unroll
        for (int q = 0; q < 4; q++) {
            int kk = ar_half * 16 + q * 4;
            dst[(kk + 0) * ASTR + ar_row] = af[q].x;
            dst[(kk + 1) * ASTR + ar_row] = af[q].y;
            dst[(kk + 2) * ASTR + ar_row] = af[q].z;
            dst[(kk + 3) * ASTR + ar_row] = af[q].w;
        }
    };
    auto issueW = [&](int t, int buf) {
        int s, k0; map_tile(t, s, k0);
        const float* wp = segs[s].W + (size_t)k0 * BN;
        uint32_t sa = (uint32_t)__cvta_generic_to_shared(Wsm + buf * (BK * BN));
        #pragma unroll
        for (int ps = 0; ps < WPASS; ps++) {
            int i = tid * 4 + ps * 1024;
            cp16(sa + i * 4, wp + i);
        }
    };

    unsigned long long acc2[4][8];
    #pragma unroll
    for (int p = 0; p < 4; p++)
        #pragma unroll
        for (int j = 0; j < 8; j++) acc2[p][j] = 0ull;

    issueA(ts); storeA(0); issueW(ts, 0); cp_commit();
    if (ts + 1 < te) issueA(ts + 1);
    cp_wait0();
    __syncthreads();

    for (int t = ts; t < te; t++) {
        int buf = (t - ts) & 1;
        if (t + 1 < te) { issueW(t + 1, buf ^ 1); cp_commit(); storeA(buf ^ 1); }
        if (t + 2 < te) issueA(t + 2);

        const float* as = As  + buf * (BK * ASTR);
        const float* ws = Wsm + buf * (BK * BN);
        #pragma unroll
        for (int k = 0; k < BK; k++) {
            ulonglong2 alo = *(const ulonglong2*)(as + k * ASTR + ty * 4);
            ulonglong2 ahi = *(const ulonglong2*)(as + k * ASTR + BM / 2 + ty * 4);
            float4 wlo = *(const float4*)(ws + k * BN + tx * 4);
            float4 whi = *(const float4*)(ws + k * BN + BN / 2 + tx * 4);
            unsigned long long ar[4] = {alo.x, alo.y, ahi.x, ahi.y};
            unsigned long long bd[8] = {
                pack2(wlo.x), pack2(wlo.y), pack2(wlo.z), pack2(wlo.w),
                pack2(whi.x), pack2(whi.y), pack2(whi.z), pack2(whi.w)};
            #pragma unroll
            for (int p = 0; p < 4; p++)
                #pragma unroll
                for (int j = 0; j < 8; j++)
                    ffma2(acc2[p][j], ar[p], bd[j]);
        }
        cp_wait0();
        __syncthreads();
    }

    float bv[8];
    if (OUT == 1) {
        #pragma unroll
        for (int j = 0; j < 4; j++) {
            bv[j]     = bias ? bias[tx * 4 + j] : 0.f;
            bv[4 + j] = bias ? bias[BN / 2 + tx * 4 + j] : 0.f;
        }
    }
    #pragma unroll
    for (int h = 0; h < 8; h++) {
        int hh = h & 3;
        int p  = ((h >> 2) << 1) | (hh >> 1);
        int c  = hh & 1;
        int rl = (h < 4) ? (ty * 4 + hh) : (BM / 2 + ty * 4 + hh);
        if (row0 + rl < M) {
            float* op = out + (size_t)sidx[rl] * BN;
            if (OUT == 2) {
                float v0 = sel2(acc2[p][0], c), v1 = sel2(acc2[p][1], c);
                float v2 = sel2(acc2[p][2], c), v3 = sel2(acc2[p][3], c);
                asm volatile("red.global.add.v4.f32 [%0], {%1,%2,%3,%4};"
                             :: "l"(op + tx * 4), "f"(v0), "f"(v1), "f"(v2), "f"(v3)
                             : "memory");
                float u0 = sel2(acc2[p][4], c), u1 = sel2(acc2[p][5], c);
                float u2 = sel2(acc2[p][6], c), u3 = sel2(acc2[p][7], c);
                asm volatile("red.global.add.v4.f32 [%0], {%1,%2,%3,%4};"
                             :: "l"(op + BN / 2 + tx * 4), "f"(u0), "f"(u1), "f"(u2), "f"(u3)
                             : "memory");
            } else {
                float4 o0, o1;
                o0.x = sel2(acc2[p][0], c) + bv[0];
                o0.y = sel2(acc2[p][1], c) + bv[1];
                o0.z = sel2(acc2[p][2], c) + bv[2];
                o0.w = sel2(acc2[p][3], c) + bv[3];
                o1.x = sel2(acc2[p][4], c) + bv[4];
                o1.y = sel2(acc2[p][5], c) + bv[5];
                o1.z = sel2(acc2[p][6], c) + bv[6];
                o1.w = sel2(acc2[p][7], c) + bv[7];
                if (relu_out) {
                    o0.x = fmaxf(o0.x, 0.f); o0.y = fmaxf(o0.y, 0.f);
                    o0.z = fmaxf(o0.z, 0.f); o0.w = fmaxf(o0.w, 0.f);
                    o1.x = fmaxf(o1.x, 0.f); o1.y = fmaxf(o1.y, 0.f);
                    o1.z = fmaxf(o1.z, 0.f); o1.w = fmaxf(o1.w, 0.f);
                }
                *(float4*)(op + tx * 4) = o0;
                *(float4*)(op + BN / 2 + tx * 4) = o1;
            }
        }
    }
}

// ---------------- layer-3 master kernels ----------------

__global__ __launch_bounds__(256) void master_node_kernel(
    const float* __restrict__ x2, const float* __restrict__ ws3,
    const float* __restrict__ bs3, float* __restrict__ out)
{
    int g = blockIdx.x;
    int c = threadIdx.x;
    const float* xr = x2 + (size_t)g * NODES_PER_GRAPH * 128;
    float acc = bs3[c];
    #pragma unroll 8
    for (int k = 0; k < 128; k++)
        acc += fmaxf(xr[k], 0.f) * ws3[(size_t)k * 256 + c];
    out[(size_t)g * 256 + c] = acc;
}

// out[g] += relu_x2[src]@wmx3 + e2@wme3 over list3 positions (warp per edge)
__global__ __launch_bounds__(256) void master_edge3_kernel(
    const float* __restrict__ x2,
    const int* __restrict__ src, const int* __restrict__ dst,
    const float* __restrict__ wmx3, const float* __restrict__ wme3,
    float* __restrict__ out)
{
    int cnt = d_cnt[2];
    int lane = threadIdx.x & 31;
    for (int i = blockIdx.x * 8 + (threadIdx.x >> 5); i < cnt; i += gridDim.x * 8) {
        int e  = d_list3[i];
        int sh = src[e];
        int g  = dst[e] / NODES_PER_GRAPH;
        float acc[8];
        #pragma unroll
        for (int j = 0; j < 8; j++) acc[j] = 0.f;
        const float* xr = x2 + (size_t)sh * 128;
        for (int k = 0; k < 128; k++) {
            float a = fmaxf(xr[k], 0.f);
            const float* wr = wmx3 + (size_t)k * 256;
            #pragma unroll
            for (int j = 0; j < 8; j++) acc[j] += a * wr[lane + j * 32];
        }
        const float* er = g_e2c + (size_t)i * 64;
        for (int k = 0; k < 64; k++) {
            float a = er[k];
            const float* wr = wme3 + (size_t)k * 256;
            #pragma unroll
            for (int j = 0; j < 8; j++) acc[j] += a * wr[lane + j * 32];
        }
        float* op = out + (size_t)g * 256;
        #pragma unroll
        for (int j = 0; j < 8; j++) atomicAdd(op + lane + j * 32, acc[j]);
    }
}

template<int BM, int BN, int BK, int NSEG>
static int smem_bytes() {
    constexpr int ASTR = BM + 4;
    return (2 * BK * ASTR + 2 * BK * BN) * 4 + NSEG * BM * 4 + BM * 4;
}

extern "C" void kernel_launch(void* const* d_in, const int* in_sizes, int n_in,
                              void* d_out, int out_size)
{
    const float* x         = (const float*)d_in[0];
    const int*   edge_idx  = (const int*)d_in[1];
    const float* edge_attr = (const float*)d_in[2];
    const float* w_proj    = (const float*)d_in[4];
    const float* b_proj    = (const float*)d_in[5];
    const float* P[30];
    for (int i = 0; i < 30 && i < n_in; i++) P[i] = (const float*)d_in[i];

    const int* src = edge_idx;
    const int* dst = edge_idx + N_EDGES;
    float* out = (float*)d_out;

    void* p;
    cudaGetSymbolAddress(&p, g_x1);     float* x1_p    = (float*)p;
    cudaGetSymbolAddress(&p, g_x2);     float* x2_p    = (float*)p;
    cudaGetSymbolAddress(&p, g_aggx);   float* aggx_p  = (float*)p;
    cudaGetSymbolAddress(&p, g_agga);   float* agga_p  = (float*)p;
    cudaGetSymbolAddress(&p, g_aggx2);  float* aggx2_p = (float*)p;
    cudaGetSymbolAddress(&p, g_agge1);  float* agge1_p = (float*)p;
    cudaGetSymbolAddress(&p, g_ec);     float* ec_p    = (float*)p;
    cudaGetSymbolAddress(&p, g_e1c);    float* e1c_p   = (float*)p;
    cudaGetSymbolAddress(&p, g_e2c);    float* e2c_p   = (float*)p;
    cudaGetSymbolAddress(&p, g_wpm);    float* wpm_p   = (float*)p;
    cudaGetSymbolAddress(&p, d_list2);  const int* l2  = (const int*)p;
    cudaGetSymbolAddress(&p, d_list3);  const int* l3  = (const int*)p;
    cudaGetSymbolAddress(&p, d_pos2);   const int* pos2 = (const int*)p;
    cudaGetSymbolAddress(&p, d_nlist1); const int* n1  = (const int*)p;
    cudaGetSymbolAddress(&p, d_nlist2); const int* n2  = (const int*)p;
    cudaGetSymbolAddress(&p, d_cnt);    const int* cnt = (const int*)p;
    const int* c_n2 = cnt + 0;
    const int* c_l2 = cnt + 1;
    const int* c_l3 = cnt + 2;
    const int* c_n1 = cnt + 3;

    static cudaStream_t sB = nullptr, sC = nullptr, sD = nullptr;
    static cudaEvent_t evRoot, evCW, evMark, evCSR, evL2, evN1, evSeed, evG1,
                       evS2, evE1, evX1, evE2;
    if (!sB) {
        cudaFuncSetAttribute(gemm_kernel<256, 64, 16, 1, 1>,
            cudaFuncAttributeMaxDynamicSharedMemorySize, smem_bytes<256, 64, 16, 1>());
        cudaFuncSetAttribute(gemm_kernel<256, 64, 16, 3, 2>,
            cudaFuncAttributeMaxDynamicSharedMemorySize, smem_bytes<256, 64, 16, 3>());
        cudaFuncSetAttribute(gemm_kernel<128, 128, 32, 1, 2>,
            cudaFuncAttributeMaxDynamicSharedMemorySize, smem_bytes<128, 128, 32, 1>());
        cudaFuncSetAttribute(gemm_kernel<128, 128, 32, 2, 2>,
            cudaFuncAttributeMaxDynamicSharedMemorySize, smem_bytes<128, 128, 32, 2>());
        cudaFuncSetAttribute(gemm_kernel<128, 128, 32, 3, 2>,
            cudaFuncAttributeMaxDynamicSharedMemorySize, smem_bytes<128, 128, 32, 3>());
        cudaStreamCreateWithFlags(&sB, cudaStreamNonBlocking);
        cudaStreamCreateWithFlags(&sC, cudaStreamNonBlocking);
        cudaStreamCreateWithFlags(&sD, cudaStreamNonBlocking);
        cudaEventCreateWithFlags(&evRoot, cudaEventDisableTiming);
        cudaEventCreateWithFlags(&evCW,   cudaEventDisableTiming);
        cudaEventCreateWithFlags(&evMark, cudaEventDisableTiming);
        cudaEventCreateWithFlags(&evCSR,  cudaEventDisableTiming);
        cudaEventCreateWithFlags(&evL2,   cudaEventDisableTiming);
        cudaEventCreateWithFlags(&evN1,   cudaEventDisableTiming);
        cudaEventCreateWithFlags(&evSeed, cudaEventDisableTiming);
        cudaEventCreateWithFlags(&evG1,   cudaEventDisableTiming);
        cudaEventCreateWithFlags(&evS2,   cudaEventDisableTiming);
        cudaEventCreateWithFlags(&evE1,   cudaEventDisableTiming);
        cudaEventCreateWithFlags(&evX1,   cudaEventDisableTiming);
        cudaEventCreateWithFlags(&evE2,   cudaEventDisableTiming);
    }

    Seg z = {nullptr, nullptr, nullptr, 0};
    const int NGRID = (N_NODES + 255) / 256;

    // ---- fork root: stream C does combine_w concurrently with marking ----
    cudaEventRecord(evRoot, 0);
    cudaStreamWaitEvent(sC, evRoot, 0);
    combine_w_kernel<<<129, 128, 0, sC>>>(w_proj, b_proj, P[9]);   // P[9]=wme1
    cudaEventRecord(evCW, sC);

    // ---- chain A: marking (+ fused degree count) ----
    zero_kernel<<<256, 256>>>();
    mark2_count_scan<<<1024, 256>>>(src, dst);
    cudaEventRecord(evMark, 0);

    // ---- stream D: CSR build (concurrent with list2_scan on A) ----
    cudaStreamWaitEvent(sD, evMark, 0);
    scanA_kernel<<<SCAN_NB, SCAN_B, 0, sD>>>();
    scanB_kernel<<<SCAN_NB, SCAN_B, 0, sD>>>();
    scatter_csr_kernel<<<1024, 256, 0, sD>>>(dst);
    cudaEventRecord(evCSR, sD);

    // ---- stream C: seed2 (needs nlist2) ----
    cudaStreamWaitEvent(sC, evMark, 0);
    seed2_kernel<<<256, 256, 0, sC>>>(x2_p, P[15]);
    cudaEventRecord(evS2, sC);

    // ---- chain A: list2 + sorted nodes1 ----
    list2_scan<<<1024, 256>>>(src, dst);
    cudaEventRecord(evL2, 0);
    nodes1_kernel<<<NGRID, 256>>>();
    cudaEventRecord(evN1, 0);

    // ---- stream D: seed x1 then G1 = x@ws1 (red-add), overlaps agg1 ----
    cudaStreamWaitEvent(sD, evN1, 0);
    cudaStreamWaitEvent(sD, evCW, 0);
    seed_x1_kernel<<<512, 256, 0, sD>>>(x1_p, P[7]);
    cudaEventRecord(evSeed, sD);
    {
        Seg a = {x, nullptr, P[6], 256};
        gemm_kernel<128, 128, 32, 1, 2>
            <<<dim3(CAP_N1 / 128, 1), 256, smem_bytes<128, 128, 32, 1>(), sD>>>(
            a, z, z, nullptr, 0, x1_p, n1, nullptr, c_n1);
    }
    cudaEventRecord(evG1, sD);

    // ---- chain B: e0 -> e1 (seed + split-K + relu) ----
    cudaStreamWaitEvent(sB, evL2, 0);
    {
        Seg a = {edge_attr, nullptr, w_proj, 128};
        gemm_kernel<256, 64, 16, 1, 1>
            <<<CAP_L2 / 256, 256, smem_bytes<256, 64, 16, 1>(), sB>>>(
            a, z, z, b_proj, 0, ec_p, l2, POS_GATHER, c_l2);
    }
    seed_rows64_kernel<<<256, 256, 0, sB>>>(e1c_p, P[13], c_l2);
    {
        Seg a = {x,    src,        P[10], 256};
        Seg b = {x,    dst,        P[11], 256};
        Seg c = {ec_p, POS_GATHER, P[12], 64};
        gemm_kernel<256, 64, 16, 3, 2>
            <<<dim3(CAP_L2 / 256, 2), 256, smem_bytes<256, 64, 16, 3>(), sB>>>(
            a, b, c, nullptr, 0, e1c_p, l2, POS_GATHER, c_l2);
    }
    relu_rows64_kernel<<<256, 256, 0, sB>>>(e1c_p, c_l2);
    cudaEventRecord(evE1, sB);
    seed_rows64_kernel<<<64, 256, 0, sB>>>(e2c_p, P[21], c_l3);

    // ---- chain A: CSR aggregation + G2 + relu ----
    cudaStreamWaitEvent(0, evCSR, 0);
    agg1_csr_kernel<<<2048, 256>>>(x, edge_attr, src);
    cudaStreamWaitEvent(0, evSeed, 0);
    {
        Seg a = {aggx_p, nullptr, P[8],  256};
        Seg b = {agga_p, nullptr, wpm_p, 128};
        gemm_kernel<128, 128, 32, 2, 2>
            <<<dim3(CAP_N1 / 128, 2), 256, smem_bytes<128, 128, 32, 2>()>>>(
            a, b, z, nullptr, 0, x1_p, n1, nullptr, c_n1);
    }
    cudaStreamWaitEvent(0, evG1, 0);
    relu_rows_kernel<<<512, 256>>>(x1_p);
    cudaEventRecord(evX1, 0);

    // ---- chain B: e2 (needs relu_x1 + e1c) ----
    cudaStreamWaitEvent(sB, evX1, 0);
    {
        Seg a = {x1_p,  src,   P[18], 128};
        Seg b = {x1_p,  dst,   P[19], 128};
        Seg c = {e1c_p, pos2,  P[20], 64};
        gemm_kernel<256, 64, 16, 3, 2>
            <<<dim3(CAP_L3 / 256, 4), 256, smem_bytes<256, 64, 16, 3>(), sB>>>(
            a, b, c, nullptr, 0, e2c_p, l3, POS_GATHER, c_l3);
    }
    relu_rows64_kernel<<<64, 256, 0, sB>>>(e2c_p, c_l3);
    cudaEventRecord(evE2, sB);

    // ---- chain A: layer 2 + masters ----
    cudaStreamWaitEvent(0, evE1, 0);
    cudaStreamWaitEvent(0, evS2, 0);
    agg2_kernel<<<512, 256>>>(x1_p, src, dst);
    {
        Seg a = {x1_p,    nullptr, P[14], 128};
        Seg b = {aggx2_p, nullptr, P[16], 128};
        Seg c = {agge1_p, nullptr, P[17], 64};
        gemm_kernel<128, 128, 32, 3, 2>
            <<<dim3(CAP_N2 / 128, 4), 256, smem_bytes<128, 128, 32, 3>()>>>(
            a, b, c, nullptr, 0, x2_p, n2, nullptr, c_n2);
    }
    master_node_kernel<<<N_GRAPHS, 256>>>(x2_p, P[22], P[23], out);
    cudaStreamWaitEvent(0, evE2, 0);
    master_edge3_kernel<<<128, 256>>>(x2_p, src, dst, P[24], P[25], out);
}

// round 16
// speedup vs baseline: 1.2244x; 1.0121x over previous
#include <cuda_runtime.h>
#include <cstddef>
#include <cstdint>

#define N_NODES 50000
#define N_EDGES 800000
#define N_GRAPHS 50
#define NODES_PER_GRAPH 1000

#define CAP_L2 32768      // edges into flag2 nodes (expected ~13.4K)
#define CAP_L3 4096       // master-destination edges (expected ~800)
#define CAP_N1 24576      // nodes needing x1 (expected ~14.2K)
#define CAP_N2 4096       // nodes needing x2 (expected ~850)

#define POS_GATHER ((const int*)(size_t)1)   // sentinel: use list position as row

#define SCAN_B 256
#define SCAN_NB ((N_NODES + SCAN_B - 1) / SCAN_B)   // 196

// Scratch (device globals; allocation rules forbid cudaMalloc)
__device__ float g_x1[(size_t)N_NODES * 128];
__device__ float g_x2[(size_t)N_NODES * 128];
__device__ float g_aggx[(size_t)N_NODES * 256];    // sum x[src] per dst (layer 1)
__device__ float g_agga[(size_t)N_NODES * 128];    // sum edge_attr per dst (layer 1)
__device__ float g_aggx2[(size_t)N_NODES * 128];   // sum relu_x1[src] per dst (layer 2)
__device__ float g_agge1[(size_t)N_NODES * 64];    // sum e1 per dst (layer 2)
__device__ float g_ec[(size_t)CAP_L2 * 64];        // e0 rows, list2-position indexed
__device__ float g_e1c[(size_t)CAP_L2 * 64];       // e1 rows, list2-position indexed
__device__ float g_e2c[(size_t)CAP_L3 * 64];       // e2 rows, list3-position indexed
__device__ float g_wpm[128 * 128];                 // w_proj @ wme1
__device__ float g_bpm[128];                       // b_proj @ wme1

__device__ int d_flag1[N_NODES];
__device__ int d_flag2[N_NODES];
__device__ int d_deg[N_NODES];     // FULL in-degree of every node
__device__ int d_off[N_NODES];     // CSR exclusive offsets
__device__ int d_cur[N_NODES];     // scatter cursors
__device__ int d_csr[N_EDGES];     // edge ids grouped by dst
__device__ unsigned long long d_scanstate[SCAN_NB];  // decoupled-lookback state
__device__ int d_list2[CAP_L2];
__device__ int d_list3[CAP_L3];
__device__ int d_pos2[N_EDGES];    // edge id -> list2 position (valid for list2 edges)
__device__ int d_nlist1[N_NODES];
__device__ int d_nlist2[CAP_N2];
__device__ int d_cnt[8];           // 0:n2 1:l2 2:l3 3:n1

struct Seg {
    const float* base;    // row-major [*, K]
    const int*   gather;  // applied to rowlist value; nullptr = value; POS_GATHER = position
    const float* W;       // [K, BN] row-major
    int K;
    int relu;             // relu A elements at staging time
};

__device__ __forceinline__ unsigned long long pack2(float v) {
    unsigned long long r;
    asm("mov.b64 %0, {%1, %1};" : "=l"(r) : "f"(v));
    return r;
}
__device__ __forceinline__ void ffma2(unsigned long long& d,
                                      unsigned long long a,
                                      unsigned long long b) {
    asm("fma.rn.f32x2 %0, %1, %2, %0;" : "+l"(d) : "l"(a), "l"(b));
}
__device__ __forceinline__ float sel2(unsigned long long v, int hi) {
    float2 f = *(float2*)&v; return hi ? f.y : f.x;
}
__device__ __forceinline__ void cp16(uint32_t saddr, const float* g) {
    asm volatile("cp.async.cg.shared.global [%0], [%1], 16;" :: "r"(saddr), "l"(g));
}
__device__ __forceinline__ void cp_commit() {
    asm volatile("cp.async.commit_group;" ::: "memory");
}
__device__ __forceinline__ void cp_wait0() {
    asm volatile("cp.async.wait_group 0;" ::: "memory");
}
__device__ __forceinline__ void redv4(float* p, float4 v) {
    asm volatile("red.global.add.v4.f32 [%0], {%1,%2,%3,%4};"
                 :: "l"(p), "f"(v.x), "f"(v.y), "f"(v.z), "f"(v.w) : "memory");
}

// ---------------- frontier marking / CSR build ----------------

__global__ __launch_bounds__(256) void zero_kernel()
{
    int n4 = N_NODES / 4;
    int4 z = {0, 0, 0, 0};
    for (int i = blockIdx.x * 256 + threadIdx.x; i < n4; i += gridDim.x * 256) {
        ((int4*)d_flag1)[i] = z;
        ((int4*)d_flag2)[i] = z;
        ((int4*)d_deg)[i]   = z;
    }
    int gid = blockIdx.x * 256 + threadIdx.x;
    for (int i = gid; i < SCAN_NB; i += gridDim.x * 256) d_scanstate[i] = 0ull;
    if (gid < 8) d_cnt[gid] = 0;
}

// fused: in-degree count (ALL nodes) + master-edge marking
__global__ __launch_bounds__(256) void mark2_count_scan(
    const int* __restrict__ src, const int* __restrict__ dst)
{
    int n4 = N_EDGES / 4;
    for (int i = blockIdx.x * 256 + threadIdx.x; i < n4; i += gridDim.x * 256) {
        int4 d = ((const int4*)dst)[i];
        int e = i * 4;
        #pragma unroll
        for (int q = 0; q < 4; q++) {
            int dd = (q == 0) ? d.x : (q == 1) ? d.y : (q == 2) ? d.z : d.w;
            atomicAdd(&d_deg[dd], 1);
            if (dd % NODES_PER_GRAPH == 0) {
                int s = src[e + q];
                if (atomicExch(&d_flag2[s], 1) == 0) {
                    d_flag1[s] = 1;
                    d_nlist2[atomicAdd(&d_cnt[0], 1)] = s;
                }
                d_list3[atomicAdd(&d_cnt[2], 1)] = e + q;
            }
        }
    }
    if (blockIdx.x == 0 && threadIdx.x < N_GRAPHS) {
        int v = threadIdx.x * NODES_PER_GRAPH;
        if (atomicExch(&d_flag2[v], 1) == 0) {
            d_flag1[v] = 1;
            d_nlist2[atomicAdd(&d_cnt[0], 1)] = v;
        }
    }
}

// edges into flag2 nodes -> list2 (+pos map); their srcs need x1
__global__ __launch_bounds__(256) void list2_scan(
    const int* __restrict__ src, const int* __restrict__ dst)
{
    int n4 = N_EDGES / 4;
    for (int i = blockIdx.x * 256 + threadIdx.x; i < n4; i += gridDim.x * 256) {
        int4 d = ((const int4*)dst)[i];
        int e = i * 4;
        #pragma unroll
        for (int q = 0; q < 4; q++) {
            int dd = (q == 0) ? d.x : (q == 1) ? d.y : (q == 2) ? d.z : d.w;
            int ee = e + q;
            if (d_flag2[dd]) {
                int j = atomicAdd(&d_cnt[1], 1);
                d_list2[j] = ee;
                d_pos2[ee] = j;
                d_flag1[src[ee]] = 1;
            }
        }
    }
}

// node-id-ordered compaction of flag1 -> nlist1 (order preserves CSR locality)
__global__ __launch_bounds__(256) void nodes1_kernel()
{
    int v = blockIdx.x * 256 + threadIdx.x;
    if (v < N_NODES && d_flag1[v]) {
        int i = atomicAdd(&d_cnt[3], 1);
        d_nlist1[i] = v;
    }
}

// ---- single-pass decoupled-lookback exclusive scan: d_deg -> d_off / d_cur ----

__device__ __forceinline__ int block_exscan(int v, int* wsh)
{
    int lane = threadIdx.x & 31, w = threadIdx.x >> 5;
    int s = v;
    #pragma unroll
    for (int o = 1; o < 32; o <<= 1) {
        int n = __shfl_up_sync(0xffffffffu, s, o);
        if (lane >= o) s += n;
    }
    if (lane == 31) wsh[w] = s;
    __syncthreads();
    if (w == 0 && lane < 8) {
        int v8 = wsh[lane];
        #pragma unroll
        for (int o = 1; o < 8; o <<= 1) {
            int n = __shfl_up_sync(0xffu, v8, o);
            if (lane >= o) v8 += n;
        }
        wsh[lane] = v8;
    }
    __syncthreads();
    return s - v + (w ? wsh[w - 1] : 0);
}

// state word: low 32 = value, high 32 = flag (1=partial, 2=inclusive)
__global__ __launch_bounds__(SCAN_B) void scan_fused_kernel()
{
    __shared__ int wsh[8];
    __shared__ int boff_sh;
    const int b = blockIdx.x;
    int idx = b * SCAN_B + threadIdx.x;
    int v = (idx < N_NODES) ? d_deg[idx] : 0;
    int excl = block_exscan(v, wsh);
    int total = wsh[7];               // block sum (inclusive of last warp)
    if (threadIdx.x == 0) {
        if (b == 0) {
            atomicExch(&d_scanstate[0],
                       ((unsigned long long)2 << 32) | (unsigned)total);
            boff_sh = 0;
        } else {
            atomicExch(&d_scanstate[b],
                       ((unsigned long long)1 << 32) | (unsigned)total);
            int run = 0;
            for (int pb = b - 1; pb >= 0; ) {
                unsigned long long s;
                do { s = atomicAdd(&d_scanstate[pb], 0ull); } while ((s >> 32) == 0);
                run += (int)(unsigned)s;
                if ((s >> 32) == 2) break;
                pb--;
            }
            atomicExch(&d_scanstate[b],
                       ((unsigned long long)2 << 32) | (unsigned)(run + total));
            boff_sh = run;
        }
    }
    __syncthreads();
    int off = excl + boff_sh;
    if (idx < N_NODES) { d_off[idx] = off; d_cur[idx] = off; }
}

// scatter all edges into CSR buckets by dst
__global__ __launch_bounds__(256) void scatter_csr_kernel(const int* __restrict__ dst)
{
    int n4 = N_EDGES / 4;
    for (int i = blockIdx.x * 256 + threadIdx.x; i < n4; i += gridDim.x * 256) {
        int4 d = ((const int4*)dst)[i];
        int e = i * 4;
        d_csr[atomicAdd(&d_cur[d.x], 1)] = e + 0;
        d_csr[atomicAdd(&d_cur[d.y], 1)] = e + 1;
        d_csr[atomicAdd(&d_cur[d.z], 1)] = e + 2;
        d_csr[atomicAdd(&d_cur[d.w], 1)] = e + 3;
    }
}

// W' = w_proj @ wme1 (128x128); bvec = b_proj @ wme1 (128)
__global__ __launch_bounds__(128) void combine_w_kernel(
    const float* __restrict__ w_proj, const float* __restrict__ b_proj,
    const float* __restrict__ wme1)
{
    int n = threadIdx.x;
    int k = blockIdx.x;
    float s = 0.f;
    if (k < 128) {
        for (int j = 0; j < 64; j++)
            s += w_proj[k * 64 + j] * wme1[j * 128 + n];
        g_wpm[k * 128 + n] = s;
    } else {
        for (int j = 0; j < 64; j++)
            s += b_proj[j] * wme1[j * 128 + n];
        g_bpm[n] = s;
    }
}

// layer-1 aggregation via CSR: warp per flagged node, register accumulation,
// 1-deep edge-id/src prefetch to hide the dependent-load chain
__global__ __launch_bounds__(256) void agg1_csr_kernel(
    const float* __restrict__ x, const float* __restrict__ eattr,
    const int* __restrict__ src)
{
    int n = d_cnt[3];
    int lane = threadIdx.x & 31;
    for (int i = blockIdx.x * 8 + (threadIdx.x >> 5); i < n; i += gridDim.x * 8) {
        int v   = d_nlist1[i];
        int beg = d_off[v];
        int end = beg + d_deg[v];
        float4 a0 = {0.f, 0.f, 0.f, 0.f}, a1 = a0, aa = a0;
        if (beg < end) {
            int e = d_csr[beg];
            int s = src[e];
            for (int j = beg; j < end; j++) {
                int e_n = 0, s_n = 0;
                if (j + 1 < end) { e_n = d_csr[j + 1]; s_n = src[e_n]; }
                const float4* xr = (const float4*)(x + (size_t)s * 256);
                float4 u0 = xr[lane];
                float4 u1 = xr[lane + 32];
                float4 w  = ((const float4*)(eattr + (size_t)e * 128))[lane];
                a0.x += u0.x; a0.y += u0.y; a0.z += u0.z; a0.w += u0.w;
                a1.x += u1.x; a1.y += u1.y; a1.z += u1.z; a1.w += u1.w;
                aa.x += w.x;  aa.y += w.y;  aa.z += w.z;  aa.w += w.w;
                e = e_n; s = s_n;
            }
        }
        ((float4*)(g_aggx + (size_t)v * 256))[lane]      = a0;
        ((float4*)(g_aggx + (size_t)v * 256))[lane + 32] = a1;
        ((float4*)(g_agga + (size_t)v * 128))[lane]      = aa;
    }
}

// x1[v] = bs1 + deg[v] * bvec for nlist1 nodes
__global__ __launch_bounds__(256) void seed_x1_kernel(
    float* __restrict__ x1, const float* __restrict__ bs1)
{
    int n = d_cnt[3];
    int total = n * 32;
    for (int i = blockIdx.x * 256 + threadIdx.x; i < total; i += gridDim.x * 256) {
        int r = i >> 5, c = i & 31;
        int v = d_nlist1[r];
        float dg = (float)d_deg[v];
        float4 b = ((const float4*)bs1)[c];
        float4 pv = ((const float4*)g_bpm)[c];
        float4 o = {b.x + dg * pv.x, b.y + dg * pv.y,
                    b.z + dg * pv.z, b.w + dg * pv.w};
        ((float4*)(x1 + (size_t)v * 128))[c] = o;
    }
}

// seed compact 64-wide rows [0,cnt) with bias
__global__ __launch_bounds__(256) void seed_rows64_kernel(
    float* __restrict__ buf, const float* __restrict__ bias, const int* __restrict__ cntp)
{
    int total = *cntp * 16;
    for (int i = blockIdx.x * 256 + threadIdx.x; i < total; i += gridDim.x * 256)
        ((float4*)buf)[i] = ((const float4*)bias)[i & 15];
}

// relu compact 64-wide rows [0,cnt)
__global__ __launch_bounds__(256) void relu_rows64_kernel(
    float* __restrict__ buf, const int* __restrict__ cntp)
{
    int total = *cntp * 16;
    for (int i = blockIdx.x * 256 + threadIdx.x; i < total; i += gridDim.x * 256) {
        float4 v = ((float4*)buf)[i];
        v.x = fmaxf(v.x, 0.f); v.y = fmaxf(v.y, 0.f);
        v.z = fmaxf(v.z, 0.f); v.w = fmaxf(v.w, 0.f);
        ((float4*)buf)[i] = v;
    }
}

// zero aggx2/agge1 and seed x2 = bs2 for nlist2 nodes
__global__ __launch_bounds__(256) void seed2_kernel(
    float* __restrict__ x2, const float* __restrict__ bs2)
{
    int n = d_cnt[0];
    int total = n * 80;
    float4 z = {0.f, 0.f, 0.f, 0.f};
    for (int i = blockIdx.x * 256 + threadIdx.x; i < total; i += gridDim.x * 256) {
        int r = i / 80, q = i % 80;
        int v = d_nlist2[r];
        if (q < 32)      ((float4*)(g_aggx2 + (size_t)v * 128))[q] = z;
        else if (q < 48) ((float4*)(g_agge1 + (size_t)v * 64))[q - 32] = z;
        else ((float4*)(x2 + (size_t)v * 128))[q - 48] = ((const float4*)bs2)[q - 48];
    }
}

// layer-2 aggregation over list2 positions: red-add relu(x1[src]), e1 (compact)
__global__ __launch_bounds__(256) void agg2_kernel(
    const float* __restrict__ x1,
    const int* __restrict__ src, const int* __restrict__ dst)
{
    int cnt = d_cnt[1];
    int lane = threadIdx.x & 31;
    for (int i = blockIdx.x * 8 + (threadIdx.x >> 5); i < cnt; i += gridDim.x * 8) {
        int e  = d_list2[i];
        int sh = src[e];
        int dh = dst[e];
        float4 v = ((const float4*)(x1 + (size_t)sh * 128))[lane];
        v.x = fmaxf(v.x, 0.f); v.y = fmaxf(v.y, 0.f);
        v.z = fmaxf(v.z, 0.f); v.w = fmaxf(v.w, 0.f);
        redv4(g_aggx2 + (size_t)dh * 128 + lane * 4, v);
        if (lane < 16) {
            float4 u = ((const float4*)(g_e1c + (size_t)i * 64))[lane];
            redv4(g_agge1 + (size_t)dh * 64 + lane * 4, u);
        }
    }
}

// ---------------- pipelined gather-GEMM (f32x2 FMA, 8x8 thread tile) ----------------
template<int BM, int BN, int BK, int NSEG, int OUT>
__global__ __launch_bounds__(256, 2) void gemm_kernel(
    Seg s0, Seg s1, Seg s2,
    const float* __restrict__ bias, int relu_out,
    float* __restrict__ out,
    const int* __restrict__ rowlist,
    const int* __restrict__ scat_map,
    const int* __restrict__ Mptr)
{
    constexpr int ASTR  = BM + 4;
    constexpr int WCOL  = BN / 64;
    constexpr int WPASS = (BK * BN) / 1024;

    const int M    = *Mptr;
    const int row0 = blockIdx.x * BM;
    if (row0 >= M) return;

    extern __shared__ float smem[];
    float* As   = smem;
    float* Wsm  = smem + 2 * BK * ASTR;
    int*   ridx = (int*)(Wsm + 2 * BK * BN);
    int*   sidx = ridx + NSEG * BM;

    Seg segs[3] = {s0, s1, s2};

    const int tid  = threadIdx.x;
    const int warp = tid >> 5;
    const int lane = tid & 31;

    const int wc = warp % WCOL;
    const int wr = warp / WCOL;
    const int ty = wr * 4 + (lane >> 3);
    const int tx = wc * 8 + (lane & 7);

    for (int i = tid; i < BM; i += 256) {
        int r = row0 + i;
        int rc = (r < M) ? r : row0;
        int rid = rowlist[rc];
        #pragma unroll
        for (int s = 0; s < NSEG; s++) {
            const int* g = segs[s].gather;
            ridx[s * BM + i] = (g == POS_GATHER) ? rc : (g ? g[rid] : rid);
        }
        sidx[i] = (scat_map == POS_GATHER) ? rc : (scat_map ? scat_map[rid] : rid);
    }
    __syncthreads();

    const int T0 = segs[0].K / BK;
    const int T1 = T0 + ((NSEG > 1) ? segs[1].K / BK : 0);
    const int T  = T1 + ((NSEG > 2) ? segs[2].K / BK : 0);
    const int ts = T * blockIdx.y / gridDim.y;
    const int te = T * (blockIdx.y + 1) / gridDim.y;

    const int ar_row  = (BM == 256) ? tid : (tid & (BM - 1));
    const int ar_half = (BM == 256) ? 0 : (tid >> 7);

    const float* abase[3];
    #pragma unroll
    for (int s = 0; s < NSEG; s++)
        abase[s] = segs[s].base + (size_t)ridx[s * BM + ar_row] * segs[s].K
                   + ar_half * 16;

    float4 af[4];

    auto map_tile = [&](int t, int& s, int& k0) {
        if (NSEG > 2 && t >= T1)      { s = 2; k0 = (t - T1) * BK; }
        else if (NSEG > 1 && t >= T0) { s = 1; k0 = (t - T0) * BK; }
        else                          { s = 0; k0 = t * BK; }
    };
    auto issueA = [&](int t) {
        int s, k0; map_tile(t, s, k0);
        const float* p = abase[s] + k0;
        #pragma unroll
        for (int q = 0; q < 4; q++) af[q] = *(const float4*)(p + q * 4);
    };
    auto storeA = [&](int t, int buf) {
        int s, k0; map_tile(t, s, k0);
        const int rl = segs[s].relu;
        float* dst = As + buf * (BK * ASTR);
        #pragma unroll
        for (int q = 0; q < 4; q++) {
            float4 v = af[q];
            if (rl) {
                v.x = fmaxf(v.x, 0.f); v.y = fmaxf(v.y, 0.f);
                v.z = fmaxf(v.z, 0.f); v.w = fmaxf(v.w, 0.f);
            }
            int kk = ar_half * 16 + q * 4;
            dst[(kk + 0) * ASTR + ar_row] = v.x;
            dst[(kk + 1) * ASTR + ar_row] = v.y;
            dst[(kk + 2) * ASTR + ar_row] = v.z;
            dst[(kk + 3) * ASTR + ar_row] = v.w;
        }
    };
    auto issueW = [&](int t, int buf) {
        int s, k0; map_tile(t, s, k0);
        const float* wp = segs[s].W + (size_t)k0 * BN;
        uint32_t sa = (uint32_t)__cvta_generic_to_shared(Wsm + buf * (BK * BN));
        #pragma unroll
        for (int ps = 0; ps < WPASS; ps++) {
            int i = tid * 4 + ps * 1024;
            cp16(sa + i * 4, wp + i);
        }
    };

    unsigned long long acc2[4][8];
    #pragma unroll
    for (int p = 0; p < 4; p++)
        #pragma unroll
        for (int j = 0; j < 8; j++) acc2[p][j] = 0ull;

    issueA(ts); storeA(ts, 0); issueW(ts, 0); cp_commit();
    if (ts + 1 < te) issueA(ts + 1);
    cp_wait0();
    __syncthreads();

    for (int t = ts; t < te; t++) {
        int buf = (t - ts) & 1;
        if (t + 1 < te) { issueW(t + 1, buf ^ 1); cp_commit(); storeA(t + 1, buf ^ 1); }
        if (t + 2 < te) issueA(t + 2);

        const float* as = As  + buf * (BK * ASTR);
        const float* ws = Wsm + buf * (BK * BN);
        #pragma unroll
        for (int k = 0; k < BK; k++) {
            ulonglong2 alo = *(const ulonglong2*)(as + k * ASTR + ty * 4);
            ulonglong2 ahi = *(const ulonglong2*)(as + k * ASTR + BM / 2 + ty * 4);
            float4 wlo = *(const float4*)(ws + k * BN + tx * 4);
            float4 whi = *(const float4*)(ws + k * BN + BN / 2 + tx * 4);
            unsigned long long ar[4] = {alo.x, alo.y, ahi.x, ahi.y};
            unsigned long long bd[8] = {
                pack2(wlo.x), pack2(wlo.y), pack2(wlo.z), pack2(wlo.w),
                pack2(whi.x), pack2(whi.y), pack2(whi.z), pack2(whi.w)};
            #pragma unroll
            for (int p = 0; p < 4; p++)
                #pragma unroll
                for (int j = 0; j < 8; j++)
                    ffma2(acc2[p][j], ar[p], bd[j]);
        }
        cp_wait0();
        __syncthreads();
    }

    float bv[8];
    if (OUT == 1) {
        #pragma unroll
        for (int j = 0; j < 4; j++) {
            bv[j]     = bias ? bias[tx * 4 + j] : 0.f;
            bv[4 + j] = bias ? bias[BN / 2 + tx * 4 + j] : 0.f;
        }
    }
    #pragma unroll
    for (int h = 0; h < 8; h++) {
        int hh = h & 3;
        int p  = ((h >> 2) << 1) | (hh >> 1);
        int c  = hh & 1;
        int rl = (h < 4) ? (ty * 4 + hh) : (BM / 2 + ty * 4 + hh);
        if (row0 + rl < M) {
            float* op = out + (size_t)sidx[rl] * BN;
            if (OUT == 2) {
                float v0 = sel2(acc2[p][0], c), v1 = sel2(acc2[p][1], c);
                float v2 = sel2(acc2[p][2], c), v3 = sel2(acc2[p][3], c);
                asm volatile("red.global.add.v4.f32 [%0], {%1,%2,%3,%4};"
                             :: "l"(op + tx * 4), "f"(v0), "f"(v1), "f"(v2), "f"(v3)
                             : "memory");
                float u0 = sel2(acc2[p][4], c), u1 = sel2(acc2[p][5], c);
                float u2 = sel2(acc2[p][6], c), u3 = sel2(acc2[p][7], c);
                asm volatile("red.global.add.v4.f32 [%0], {%1,%2,%3,%4};"
                             :: "l"(op + BN / 2 + tx * 4), "f"(u0), "f"(u1), "f"(u2), "f"(u3)
                             : "memory");
            } else {
                float4 o0, o1;
                o0.x = sel2(acc2[p][0], c) + bv[0];
                o0.y = sel2(acc2[p][1], c) + bv[1];
                o0.z = sel2(acc2[p][2], c) + bv[2];
                o0.w = sel2(acc2[p][3], c) + bv[3];
                o1.x = sel2(acc2[p][4], c) + bv[4];
                o1.y = sel2(acc2[p][5], c) + bv[5];
                o1.z = sel2(acc2[p][6], c) + bv[6];
                o1.w = sel2(acc2[p][7], c) + bv[7];
                if (relu_out) {
                    o0.x = fmaxf(o0.x, 0.f); o0.y = fmaxf(o0.y, 0.f);
                    o0.z = fmaxf(o0.z, 0.f); o0.w = fmaxf(o0.w, 0.f);
                    o1.x = fmaxf(o1.x, 0.f); o1.y = fmaxf(o1.y, 0.f);
                    o1.z = fmaxf(o1.z, 0.f); o1.w = fmaxf(o1.w, 0.f);
                }
                *(float4*)(op + tx * 4) = o0;
                *(float4*)(op + BN / 2 + tx * 4) = o1;
            }
        }
    }
}

// ---------------- layer-3 master kernels ----------------

__global__ __launch_bounds__(256) void master_node_kernel(
    const float* __restrict__ x2, const float* __restrict__ ws3,
    const float* __restrict__ bs3, float* __restrict__ out)
{
    int g = blockIdx.x;
    int c = threadIdx.x;
    const float* xr = x2 + (size_t)g * NODES_PER_GRAPH * 128;
    float acc = bs3[c];
    #pragma unroll 8
    for (int k = 0; k < 128; k++)
        acc += fmaxf(xr[k], 0.f) * ws3[(size_t)k * 256 + c];
    out[(size_t)g * 256 + c] = acc;
}

// out[g] += relu_x2[src]@wmx3 + e2@wme3 over list3 positions (warp per edge)
__global__ __launch_bounds__(256) void master_edge3_kernel(
    const float* __restrict__ x2,
    const int* __restrict__ src, const int* __restrict__ dst,
    const float* __restrict__ wmx3, const float* __restrict__ wme3,
    float* __restrict__ out)
{
    int cnt = d_cnt[2];
    int lane = threadIdx.x & 31;
    for (int i = blockIdx.x * 8 + (threadIdx.x >> 5); i < cnt; i += gridDim.x * 8) {
        int e  = d_list3[i];
        int sh = src[e];
        int g  = dst[e] / NODES_PER_GRAPH;
        float acc[8];
        #pragma unroll
        for (int j = 0; j < 8; j++) acc[j] = 0.f;
        const float* xr = x2 + (size_t)sh * 128;
        for (int k = 0; k < 128; k++) {
            float a = fmaxf(xr[k], 0.f);
            const float* wr = wmx3 + (size_t)k * 256;
            #pragma unroll
            for (int j = 0; j < 8; j++) acc[j] += a * wr[lane + j * 32];
        }
        const float* er = g_e2c + (size_t)i * 64;
        for (int k = 0; k < 64; k++) {
            float a = er[k];
            const float* wr = wme3 + (size_t)k * 256;
            #pragma unroll
            for (int j = 0; j < 8; j++) acc[j] += a * wr[lane + j * 32];
        }
        float* op = out + (size_t)g * 256;
        #pragma unroll
        for (int j = 0; j < 8; j++) atomicAdd(op + lane + j * 32, acc[j]);
    }
}

template<int BM, int BN, int BK, int NSEG>
static int smem_bytes() {
    constexpr int ASTR = BM + 4;
    return (2 * BK * ASTR + 2 * BK * BN) * 4 + NSEG * BM * 4 + BM * 4;
}

extern "C" void kernel_launch(void* const* d_in, const int* in_sizes, int n_in,
                              void* d_out, int out_size)
{
    const float* x         = (const float*)d_in[0];
    const int*   edge_idx  = (const int*)d_in[1];
    const float* edge_attr = (const float*)d_in[2];
    const float* w_proj    = (const float*)d_in[4];
    const float* b_proj    = (const float*)d_in[5];
    const float* P[30];
    for (int i = 0; i < 30 && i < n_in; i++) P[i] = (const float*)d_in[i];

    const int* src = edge_idx;
    const int* dst = edge_idx + N_EDGES;
    float* out = (float*)d_out;

    void* p;
    cudaGetSymbolAddress(&p, g_x1);     float* x1_p    = (float*)p;
    cudaGetSymbolAddress(&p, g_x2);     float* x2_p    = (float*)p;
    cudaGetSymbolAddress(&p, g_aggx);   float* aggx_p  = (float*)p;
    cudaGetSymbolAddress(&p, g_agga);   float* agga_p  = (float*)p;
    cudaGetSymbolAddress(&p, g_aggx2);  float* aggx2_p = (float*)p;
    cudaGetSymbolAddress(&p, g_agge1);  float* agge1_p = (float*)p;
    cudaGetSymbolAddress(&p, g_ec);     float* ec_p    = (float*)p;
    cudaGetSymbolAddress(&p, g_e1c);    float* e1c_p   = (float*)p;
    cudaGetSymbolAddress(&p, g_e2c);    float* e2c_p   = (float*)p;
    cudaGetSymbolAddress(&p, g_wpm);    float* wpm_p   = (float*)p;
    cudaGetSymbolAddress(&p, d_list2);  const int* l2  = (const int*)p;
    cudaGetSymbolAddress(&p, d_list3);  const int* l3  = (const int*)p;
    cudaGetSymbolAddress(&p, d_pos2);   const int* pos2 = (const int*)p;
    cudaGetSymbolAddress(&p, d_nlist1); const int* n1  = (const int*)p;
    cudaGetSymbolAddress(&p, d_nlist2); const int* n2  = (const int*)p;
    cudaGetSymbolAddress(&p, d_cnt);    const int* cnt = (const int*)p;
    const int* c_n2 = cnt + 0;
    const int* c_l2 = cnt + 1;
    const int* c_l3 = cnt + 2;
    const int* c_n1 = cnt + 3;

    static cudaStream_t sB = nullptr, sC = nullptr, sD = nullptr;
    static cudaEvent_t evRoot, evCW, evMark, evCSR, evL2, evN1, evSeed, evG1,
                       evS2, evE1, evX1, evE2;
    if (!sB) {
        cudaFuncSetAttribute(gemm_kernel<256, 64, 16, 1, 1>,
            cudaFuncAttributeMaxDynamicSharedMemorySize, smem_bytes<256, 64, 16, 1>());
        cudaFuncSetAttribute(gemm_kernel<256, 64, 16, 3, 2>,
            cudaFuncAttributeMaxDynamicSharedMemorySize, smem_bytes<256, 64, 16, 3>());
        cudaFuncSetAttribute(gemm_kernel<128, 128, 32, 1, 2>,
            cudaFuncAttributeMaxDynamicSharedMemorySize, smem_bytes<128, 128, 32, 1>());
        cudaFuncSetAttribute(gemm_kernel<128, 128, 32, 2, 2>,
            cudaFuncAttributeMaxDynamicSharedMemorySize, smem_bytes<128, 128, 32, 2>());
        cudaFuncSetAttribute(gemm_kernel<128, 128, 32, 3, 2>,
            cudaFuncAttributeMaxDynamicSharedMemorySize, smem_bytes<128, 128, 32, 3>());
        cudaStreamCreateWithFlags(&sB, cudaStreamNonBlocking);
        cudaStreamCreateWithFlags(&sC, cudaStreamNonBlocking);
        cudaStreamCreateWithFlags(&sD, cudaStreamNonBlocking);
        cudaEventCreateWithFlags(&evRoot, cudaEventDisableTiming);
        cudaEventCreateWithFlags(&evCW,   cudaEventDisableTiming);
        cudaEventCreateWithFlags(&evMark, cudaEventDisableTiming);
        cudaEventCreateWithFlags(&evCSR,  cudaEventDisableTiming);
        cudaEventCreateWithFlags(&evL2,   cudaEventDisableTiming);
        cudaEventCreateWithFlags(&evN1,   cudaEventDisableTiming);
        cudaEventCreateWithFlags(&evSeed, cudaEventDisableTiming);
        cudaEventCreateWithFlags(&evG1,   cudaEventDisableTiming);
        cudaEventCreateWithFlags(&evS2,   cudaEventDisableTiming);
        cudaEventCreateWithFlags(&evE1,   cudaEventDisableTiming);
        cudaEventCreateWithFlags(&evX1,   cudaEventDisableTiming);
        cudaEventCreateWithFlags(&evE2,   cudaEventDisableTiming);
    }

    Seg z = {nullptr, nullptr, nullptr, 0, 0};
    const int NGRID = (N_NODES + 255) / 256;

    // ---- fork root: stream C does combine_w concurrently with marking ----
    cudaEventRecord(evRoot, 0);
    cudaStreamWaitEvent(sC, evRoot, 0);
    combine_w_kernel<<<129, 128, 0, sC>>>(w_proj, b_proj, P[9]);   // P[9]=wme1
    cudaEventRecord(evCW, sC);

    // ---- chain A: marking (+ fused degree count) ----
    zero_kernel<<<256, 256>>>();
    mark2_count_scan<<<1024, 256>>>(src, dst);
    cudaEventRecord(evMark, 0);

    // ---- stream D: CSR build (single-pass scan + scatter) ----
    cudaStreamWaitEvent(sD, evMark, 0);
    scan_fused_kernel<<<SCAN_NB, SCAN_B, 0, sD>>>();
    scatter_csr_kernel<<<1024, 256, 0, sD>>>(dst);
    cudaEventRecord(evCSR, sD);

    // ---- stream C: seed2 (needs nlist2) ----
    cudaStreamWaitEvent(sC, evMark, 0);
    seed2_kernel<<<256, 256, 0, sC>>>(x2_p, P[15]);
    cudaEventRecord(evS2, sC);

    // ---- chain A: list2 + sorted nodes1 ----
    list2_scan<<<1024, 256>>>(src, dst);
    cudaEventRecord(evL2, 0);
    nodes1_kernel<<<NGRID, 256>>>();
    cudaEventRecord(evN1, 0);

    // ---- stream D: seed x1 then G1 = x@ws1 (red-add), overlaps agg1 ----
    cudaStreamWaitEvent(sD, evN1, 0);
    cudaStreamWaitEvent(sD, evCW, 0);
    seed_x1_kernel<<<512, 256, 0, sD>>>(x1_p, P[7]);
    cudaEventRecord(evSeed, sD);
    {
        Seg a = {x, nullptr, P[6], 256, 0};
        gemm_kernel<128, 128, 32, 1, 2>
            <<<dim3(CAP_N1 / 128, 1), 256, smem_bytes<128, 128, 32, 1>(), sD>>>(
            a, z, z, nullptr, 0, x1_p, n1, nullptr, c_n1);
    }
    cudaEventRecord(evG1, sD);

    // ---- chain B: e0 -> e1 (seed + split-K + relu) ----
    cudaStreamWaitEvent(sB, evL2, 0);
    {
        Seg a = {edge_attr, nullptr, w_proj, 128, 0};
        gemm_kernel<256, 64, 16, 1, 1>
            <<<CAP_L2 / 256, 256, smem_bytes<256, 64, 16, 1>(), sB>>>(
            a, z, z, b_proj, 0, ec_p, l2, POS_GATHER, c_l2);
    }
    seed_rows64_kernel<<<256, 256, 0, sB>>>(e1c_p, P[13], c_l2);
    {
        Seg a = {x,    src,        P[10], 256, 0};
        Seg b = {x,    dst,        P[11], 256, 0};
        Seg c = {ec_p, POS_GATHER, P[12], 64,  0};
        gemm_kernel<256, 64, 16, 3, 2>
            <<<dim3(CAP_L2 / 256, 2), 256, smem_bytes<256, 64, 16, 3>(), sB>>>(
            a, b, c, nullptr, 0, e1c_p, l2, POS_GATHER, c_l2);
    }
    relu_rows64_kernel<<<256, 256, 0, sB>>>(e1c_p, c_l2);
    cudaEventRecord(evE1, sB);
    seed_rows64_kernel<<<64, 256, 0, sB>>>(e2c_p, P[21], c_l3);

    // ---- chain A: CSR aggregation + G2 (x1 stays pre-relu in memory) ----
    cudaStreamWaitEvent(0, evCSR, 0);
    agg1_csr_kernel<<<2048, 256>>>(x, edge_attr, src);
    cudaStreamWaitEvent(0, evSeed, 0);
    {
        Seg a = {aggx_p, nullptr, P[8],  256, 0};
        Seg b = {agga_p, nullptr, wpm_p, 128, 0};
        gemm_kernel<128, 128, 32, 2, 2>
            <<<dim3(CAP_N1 / 128, 2), 256, smem_bytes<128, 128, 32, 2>()>>>(
            a, b, z, nullptr, 0, x1_p, n1, nullptr, c_n1);
    }
    cudaStreamWaitEvent(0, evG1, 0);
    cudaEventRecord(evX1, 0);                    // x1 final (pre-relu)

    // ---- chain B: e2 (relu(x1) on load; seed + split-K + relu) ----
    cudaStreamWaitEvent(sB, evX1, 0);
    {
        Seg a = {x1_p,  src,   P[18], 128, 1};
        Seg b = {x1_p,  dst,   P[19], 128, 1};
        Seg c = {e1c_p, pos2,  P[20], 64,  0};
        gemm_kernel<256, 64, 16, 3, 2>
            <<<dim3(CAP_L3 / 256, 4), 256, smem_bytes<256, 64, 16, 3>(), sB>>>(
            a, b, c, nullptr, 0, e2c_p, l3, POS_GATHER, c_l3);
    }
    relu_rows64_kernel<<<64, 256, 0, sB>>>(e2c_p, c_l3);
    cudaEventRecord(evE2, sB);

    // ---- chain A: layer 2 + masters ----
    cudaStreamWaitEvent(0, evE1, 0);
    cudaStreamWaitEvent(0, evS2, 0);
    agg2_kernel<<<512, 256>>>(x1_p, src, dst);   // relu applied inline
    {
        Seg a = {x1_p,    nullptr, P[14], 128, 1};
        Seg b = {aggx2_p, nullptr, P[16], 128, 0};
        Seg c = {agge1_p, nullptr, P[17], 64,  0};
        gemm_kernel<128, 128, 32, 3, 2>
            <<<dim3(CAP_N2 / 128, 4), 256, smem_bytes<128, 128, 32, 3>()>>>(
            a, b, c, nullptr, 0, x2_p, n2, nullptr, c_n2);
    }
    master_node_kernel<<<N_GRAPHS, 256>>>(x2_p, P[22], P[23], out);
    cudaStreamWaitEvent(0, evE2, 0);
    master_edge3_kernel<<<128, 256>>>(x2_p, src, dst, P[24], P[25], out);
}

// round 17
// speedup vs baseline: 1.2312x; 1.0055x over previous
#include <cuda_runtime.h>
#include <cstddef>
#include <cstdint>

#define N_NODES 50000
#define N_EDGES 800000
#define N_GRAPHS 50
#define NODES_PER_GRAPH 1000

#define CAP_L2 32768      // edges into flag2 nodes (expected ~13.4K)
#define CAP_L3 4096       // master-destination edges (expected ~800)
#define CAP_N1 24576      // nodes needing x1 (expected ~14.2K)
#define CAP_N2 4096       // nodes needing x2 (expected ~850)

#define POS_GATHER ((const int*)(size_t)1)   // sentinel: use list position as row

#define SCAN_B 256
#define SCAN_NB ((N_NODES + SCAN_B - 1) / SCAN_B)   // 196

// Scratch (device globals; allocation rules forbid cudaMalloc)
__device__ float g_x1[(size_t)N_NODES * 128];
__device__ float g_x2[(size_t)N_NODES * 128];
__device__ float g_aggx[(size_t)N_NODES * 256];    // sum x[src] per dst (layer 1)
__device__ float g_agga[(size_t)N_NODES * 128];    // sum edge_attr per dst (layer 1)
__device__ float g_aggx2[(size_t)N_NODES * 128];   // sum relu_x1[src] per dst (layer 2)
__device__ float g_agge1[(size_t)N_NODES * 64];    // sum e1 per dst (layer 2)
__device__ float g_ec[(size_t)CAP_L2 * 64];        // e0 rows, list2-position indexed
__device__ float g_e1c[(size_t)CAP_L2 * 64];       // e1 rows, list2-position indexed
__device__ float g_e2c[(size_t)CAP_L3 * 64];       // e2 rows, list3-position indexed
__device__ float g_wpm[128 * 128];                 // w_proj @ wme1
__device__ float g_bpm[128];                       // b_proj @ wme1

__device__ int d_flag1[N_NODES];
__device__ int d_flag2[N_NODES];
__device__ int d_deg[N_NODES];     // FULL in-degree of every node
__device__ int d_off[N_NODES];     // CSR exclusive offsets
__device__ int d_cur[N_NODES];     // scatter cursors
__device__ int d_csr[N_EDGES];     // edge ids grouped by dst
__device__ unsigned long long d_scanstate[SCAN_NB];  // decoupled-lookback state
__device__ int d_list2[CAP_L2];
__device__ int d_list3[CAP_L3];
__device__ int d_pos2[N_EDGES];    // edge id -> list2 position (valid for list2 edges)
__device__ int d_nlist1[N_NODES];
__device__ int d_nlist2[CAP_N2];
__device__ int d_cnt[8];           // 0:n2 1:l2 2:l3 3:n1

struct Seg {
    const float* base;    // row-major [*, K]
    const int*   gather;  // applied to rowlist value; nullptr = value; POS_GATHER = position
    const float* W;       // [K, BN] row-major
    int K;
    int relu;             // relu A elements at staging time
};

__device__ __forceinline__ unsigned long long pack2(float v) {
    unsigned long long r;
    asm("mov.b64 %0, {%1, %1};" : "=l"(r) : "f"(v));
    return r;
}
__device__ __forceinline__ void ffma2(unsigned long long& d,
                                      unsigned long long a,
                                      unsigned long long b) {
    asm("fma.rn.f32x2 %0, %1, %2, %0;" : "+l"(d) : "l"(a), "l"(b));
}
__device__ __forceinline__ float sel2(unsigned long long v, int hi) {
    float2 f = *(float2*)&v; return hi ? f.y : f.x;
}
__device__ __forceinline__ void cp16(uint32_t saddr, const float* g) {
    asm volatile("cp.async.cg.shared.global [%0], [%1], 16;" :: "r"(saddr), "l"(g));
}
__device__ __forceinline__ void cp_commit() {
    asm volatile("cp.async.commit_group;" ::: "memory");
}
__device__ __forceinline__ void cp_wait0() {
    asm volatile("cp.async.wait_group 0;" ::: "memory");
}
__device__ __forceinline__ void redv4(float* p, float4 v) {
    asm volatile("red.global.add.v4.f32 [%0], {%1,%2,%3,%4};"
                 :: "l"(p), "f"(v.x), "f"(v.y), "f"(v.z), "f"(v.w) : "memory");
}

// ---------------- frontier marking / CSR build ----------------

__global__ __launch_bounds__(256) void zero_kernel()
{
    int n4 = N_NODES / 4;
    int4 z = {0, 0, 0, 0};
    for (int i = blockIdx.x * 256 + threadIdx.x; i < n4; i += gridDim.x * 256) {
        ((int4*)d_flag1)[i] = z;
        ((int4*)d_flag2)[i] = z;
        ((int4*)d_deg)[i]   = z;
    }
    int gid = blockIdx.x * 256 + threadIdx.x;
    for (int i = gid; i < SCAN_NB; i += gridDim.x * 256) d_scanstate[i] = 0ull;
    if (gid < 8) d_cnt[gid] = 0;
}

// fused: in-degree count (ALL nodes) + master-edge marking
__global__ __launch_bounds__(256) void mark2_count_scan(
    const int* __restrict__ src, const int* __restrict__ dst)
{
    int n4 = N_EDGES / 4;
    for (int i = blockIdx.x * 256 + threadIdx.x; i < n4; i += gridDim.x * 256) {
        int4 d = ((const int4*)dst)[i];
        int e = i * 4;
        #pragma unroll
        for (int q = 0; q < 4; q++) {
            int dd = (q == 0) ? d.x : (q == 1) ? d.y : (q == 2) ? d.z : d.w;
            atomicAdd(&d_deg[dd], 1);
            if (dd % NODES_PER_GRAPH == 0) {
                int s = src[e + q];
                if (atomicExch(&d_flag2[s], 1) == 0) {
                    d_flag1[s] = 1;
                    d_nlist2[atomicAdd(&d_cnt[0], 1)] = s;
                }
                d_list3[atomicAdd(&d_cnt[2], 1)] = e + q;
            }
        }
    }
    if (blockIdx.x == 0 && threadIdx.x < N_GRAPHS) {
        int v = threadIdx.x * NODES_PER_GRAPH;
        if (atomicExch(&d_flag2[v], 1) == 0) {
            d_flag1[v] = 1;
            d_nlist2[atomicAdd(&d_cnt[0], 1)] = v;
        }
    }
}

// edges into flag2 nodes -> list2 (+pos map); their srcs need x1
__global__ __launch_bounds__(256) void list2_scan(
    const int* __restrict__ src, const int* __restrict__ dst)
{
    int n4 = N_EDGES / 4;
    for (int i = blockIdx.x * 256 + threadIdx.x; i < n4; i += gridDim.x * 256) {
        int4 d = ((const int4*)dst)[i];
        int e = i * 4;
        #pragma unroll
        for (int q = 0; q < 4; q++) {
            int dd = (q == 0) ? d.x : (q == 1) ? d.y : (q == 2) ? d.z : d.w;
            int ee = e + q;
            if (d_flag2[dd]) {
                int j = atomicAdd(&d_cnt[1], 1);
                d_list2[j] = ee;
                d_pos2[ee] = j;
                d_flag1[src[ee]] = 1;
            }
        }
    }
}

// node-id-ordered compaction of flag1 -> nlist1 (order preserves CSR locality)
__global__ __launch_bounds__(256) void nodes1_kernel()
{
    int v = blockIdx.x * 256 + threadIdx.x;
    if (v < N_NODES && d_flag1[v]) {
        int i = atomicAdd(&d_cnt[3], 1);
        d_nlist1[i] = v;
    }
}

// ---- single-pass decoupled-lookback exclusive scan: d_deg -> d_off / d_cur ----

__device__ __forceinline__ int block_exscan(int v, int* wsh)
{
    int lane = threadIdx.x & 31, w = threadIdx.x >> 5;
    int s = v;
    #pragma unroll
    for (int o = 1; o < 32; o <<= 1) {
        int n = __shfl_up_sync(0xffffffffu, s, o);
        if (lane >= o) s += n;
    }
    if (lane == 31) wsh[w] = s;
    __syncthreads();
    if (w == 0 && lane < 8) {
        int v8 = wsh[lane];
        #pragma unroll
        for (int o = 1; o < 8; o <<= 1) {
            int n = __shfl_up_sync(0xffu, v8, o);
            if (lane >= o) v8 += n;
        }
        wsh[lane] = v8;
    }
    __syncthreads();
    return s - v + (w ? wsh[w - 1] : 0);
}

// state word: low 32 = value, high 32 = flag (1=partial, 2=inclusive)
// warp-parallel lookback: warp 0 scans 32 predecessors per step
__global__ __launch_bounds__(SCAN_B) void scan_fused_kernel()
{
    __shared__ int wsh[8];
    __shared__ int boff_sh;
    const int b = blockIdx.x;
    int idx = b * SCAN_B + threadIdx.x;
    int v = (idx < N_NODES) ? d_deg[idx] : 0;
    int excl = block_exscan(v, wsh);
    int total = wsh[7];
    const int lane = threadIdx.x & 31;
    if (threadIdx.x < 32) {
        if (b == 0) {
            if (lane == 0) {
                atomicExch(&d_scanstate[0],
                           ((unsigned long long)2 << 32) | (unsigned)total);
                boff_sh = 0;
            }
        } else {
            if (lane == 0)
                atomicExch(&d_scanstate[b],
                           ((unsigned long long)1 << 32) | (unsigned)total);
            __syncwarp();
            int run = 0;
            for (int base = b - 1; base >= 0; base -= 32) {
                int pb = base - lane;
                int flag = 2, val = 0;
                if (pb >= 0) {
                    unsigned long long s;
                    do { s = atomicAdd(&d_scanstate[pb], 0ull); } while ((s >> 32) == 0);
                    flag = (int)(s >> 32);
                    val  = (int)(unsigned)s;
                }
                unsigned pmask = __ballot_sync(0xffffffffu, flag == 2 && pb >= 0);
                int firstp = pmask ? (__ffs(pmask) - 1) : 32;   // nearest inclusive
                int contrib = (pb >= 0 && lane <= firstp) ? val : 0;
                #pragma unroll
                for (int o = 16; o > 0; o >>= 1)
                    contrib += __shfl_down_sync(0xffffffffu, contrib, o);
                contrib = __shfl_sync(0xffffffffu, contrib, 0);
                run += contrib;
                if (firstp < 32) break;
            }
            if (lane == 0) {
                atomicExch(&d_scanstate[b],
                           ((unsigned long long)2 << 32) | (unsigned)(run + total));
                boff_sh = run;
            }
        }
    }
    __syncthreads();
    int off = excl + boff_sh;
    if (idx < N_NODES) { d_off[idx] = off; d_cur[idx] = off; }
}

// scatter all edges into CSR buckets by dst
__global__ __launch_bounds__(256) void scatter_csr_kernel(const int* __restrict__ dst)
{
    int n4 = N_EDGES / 4;
    for (int i = blockIdx.x * 256 + threadIdx.x; i < n4; i += gridDim.x * 256) {
        int4 d = ((const int4*)dst)[i];
        int e = i * 4;
        d_csr[atomicAdd(&d_cur[d.x], 1)] = e + 0;
        d_csr[atomicAdd(&d_cur[d.y], 1)] = e + 1;
        d_csr[atomicAdd(&d_cur[d.z], 1)] = e + 2;
        d_csr[atomicAdd(&d_cur[d.w], 1)] = e + 3;
    }
}

// W' = w_proj @ wme1 (128x128); bvec = b_proj @ wme1 (128)
__global__ __launch_bounds__(128) void combine_w_kernel(
    const float* __restrict__ w_proj, const float* __restrict__ b_proj,
    const float* __restrict__ wme1)
{
    int n = threadIdx.x;
    int k = blockIdx.x;
    float s = 0.f;
    if (k < 128) {
        for (int j = 0; j < 64; j++)
            s += w_proj[k * 64 + j] * wme1[j * 128 + n];
        g_wpm[k * 128 + n] = s;
    } else {
        for (int j = 0; j < 64; j++)
            s += b_proj[j] * wme1[j * 128 + n];
        g_bpm[n] = s;
    }
}

// layer-1 aggregation via CSR: warp per flagged node, register accumulation,
// 1-deep edge-id/src prefetch to hide the dependent-load chain
__global__ __launch_bounds__(256) void agg1_csr_kernel(
    const float* __restrict__ x, const float* __restrict__ eattr,
    const int* __restrict__ src)
{
    int n = d_cnt[3];
    int lane = threadIdx.x & 31;
    for (int i = blockIdx.x * 8 + (threadIdx.x >> 5); i < n; i += gridDim.x * 8) {
        int v   = d_nlist1[i];
        int beg = d_off[v];
        int end = beg + d_deg[v];
        float4 a0 = {0.f, 0.f, 0.f, 0.f}, a1 = a0, aa = a0;
        if (beg < end) {
            int e = d_csr[beg];
            int s = src[e];
            for (int j = beg; j < end; j++) {
                int e_n = 0, s_n = 0;
                if (j + 1 < end) { e_n = d_csr[j + 1]; s_n = src[e_n]; }
                const float4* xr = (const float4*)(x + (size_t)s * 256);
                float4 u0 = xr[lane];
                float4 u1 = xr[lane + 32];
                float4 w  = ((const float4*)(eattr + (size_t)e * 128))[lane];
                a0.x += u0.x; a0.y += u0.y; a0.z += u0.z; a0.w += u0.w;
                a1.x += u1.x; a1.y += u1.y; a1.z += u1.z; a1.w += u1.w;
                aa.x += w.x;  aa.y += w.y;  aa.z += w.z;  aa.w += w.w;
                e = e_n; s = s_n;
            }
        }
        ((float4*)(g_aggx + (size_t)v * 256))[lane]      = a0;
        ((float4*)(g_aggx + (size_t)v * 256))[lane + 32] = a1;
        ((float4*)(g_agga + (size_t)v * 128))[lane]      = aa;
    }
}

// x1[v] = bs1 + deg[v] * bvec for nlist1 nodes
__global__ __launch_bounds__(256) void seed_x1_kernel(
    float* __restrict__ x1, const float* __restrict__ bs1)
{
    int n = d_cnt[3];
    int total = n * 32;
    for (int i = blockIdx.x * 256 + threadIdx.x; i < total; i += gridDim.x * 256) {
        int r = i >> 5, c = i & 31;
        int v = d_nlist1[r];
        float dg = (float)d_deg[v];
        float4 b = ((const float4*)bs1)[c];
        float4 pv = ((const float4*)g_bpm)[c];
        float4 o = {b.x + dg * pv.x, b.y + dg * pv.y,
                    b.z + dg * pv.z, b.w + dg * pv.w};
        ((float4*)(x1 + (size_t)v * 128))[c] = o;
    }
}

// seed compact 64-wide rows [0,cnt) with bias
__global__ __launch_bounds__(256) void seed_rows64_kernel(
    float* __restrict__ buf, const float* __restrict__ bias, const int* __restrict__ cntp)
{
    int total = *cntp * 16;
    for (int i = blockIdx.x * 256 + threadIdx.x; i < total; i += gridDim.x * 256)
        ((float4*)buf)[i] = ((const float4*)bias)[i & 15];
}

// relu compact 64-wide rows [0,cnt)
__global__ __launch_bounds__(256) void relu_rows64_kernel(
    float* __restrict__ buf, const int* __restrict__ cntp)
{
    int total = *cntp * 16;
    for (int i = blockIdx.x * 256 + threadIdx.x; i < total; i += gridDim.x * 256) {
        float4 v = ((float4*)buf)[i];
        v.x = fmaxf(v.x, 0.f); v.y = fmaxf(v.y, 0.f);
        v.z = fmaxf(v.z, 0.f); v.w = fmaxf(v.w, 0.f);
        ((float4*)buf)[i] = v;
    }
}

// zero aggx2/agge1 and seed x2 = bs2 for nlist2 nodes
__global__ __launch_bounds__(256) void seed2_kernel(
    float* __restrict__ x2, const float* __restrict__ bs2)
{
    int n = d_cnt[0];
    int total = n * 80;
    float4 z = {0.f, 0.f, 0.f, 0.f};
    for (int i = blockIdx.x * 256 + threadIdx.x; i < total; i += gridDim.x * 256) {
        int r = i / 80, q = i % 80;
        int v = d_nlist2[r];
        if (q < 32)      ((float4*)(g_aggx2 + (size_t)v * 128))[q] = z;
        else if (q < 48) ((float4*)(g_agge1 + (size_t)v * 64))[q - 32] = z;
        else ((float4*)(x2 + (size_t)v * 128))[q - 48] = ((const float4*)bs2)[q - 48];
    }
}

// layer-2 aggregation over list2 positions: red-add relu(x1[src]), e1 (compact)
__global__ __launch_bounds__(256) void agg2_kernel(
    const float* __restrict__ x1,
    const int* __restrict__ src, const int* __restrict__ dst)
{
    int cnt = d_cnt[1];
    int lane = threadIdx.x & 31;
    for (int i = blockIdx.x * 8 + (threadIdx.x >> 5); i < cnt; i += gridDim.x * 8) {
        int e  = d_list2[i];
        int sh = src[e];
        int dh = dst[e];
        float4 v = ((const float4*)(x1 + (size_t)sh * 128))[lane];
        v.x = fmaxf(v.x, 0.f); v.y = fmaxf(v.y, 0.f);
        v.z = fmaxf(v.z, 0.f); v.w = fmaxf(v.w, 0.f);
        redv4(g_aggx2 + (size_t)dh * 128 + lane * 4, v);
        if (lane < 16) {
            float4 u = ((const float4*)(g_e1c + (size_t)i * 64))[lane];
            redv4(g_agge1 + (size_t)dh * 64 + lane * 4, u);
        }
    }
}

// ---------------- pipelined gather-GEMM (f32x2 FMA, 8x8 thread tile) ----------------
template<int BM, int BN, int BK, int NSEG, int OUT>
__global__ __launch_bounds__(256, 2) void gemm_kernel(
    Seg s0, Seg s1, Seg s2,
    const float* __restrict__ bias, int relu_out,
    float* __restrict__ out,
    const int* __restrict__ rowlist,
    const int* __restrict__ scat_map,
    const int* __restrict__ Mptr)
{
    constexpr int ASTR  = BM + 4;
    constexpr int WCOL  = BN / 64;
    constexpr int WPASS = (BK * BN) / 1024;

    const int M    = *Mptr;
    const int row0 = blockIdx.x * BM;
    if (row0 >= M) return;

    extern __shared__ float smem[];
    float* As   = smem;
    float* Wsm  = smem + 2 * BK * ASTR;
    int*   ridx = (int*)(Wsm + 2 * BK * BN);
    int*   sidx = ridx + NSEG * BM;

    Seg segs[3] = {s0, s1, s2};

    const int tid  = threadIdx.x;
    const int warp = tid >> 5;
    const int lane = tid & 31;

    const int wc = warp % WCOL;
    const int wr = warp / WCOL;
    const int ty = wr * 4 + (lane >> 3);
    const int tx = wc * 8 + (lane & 7);

    for (int i = tid; i < BM; i += 256) {
        int r = row0 + i;
        int rc = (r < M) ? r : row0;
        int rid = rowlist[rc];
        #pragma unroll
        for (int s = 0; s < NSEG; s++) {
            const int* g = segs[s].gather;
            ridx[s * BM + i] = (g == POS_GATHER) ? rc : (g ? g[rid] : rid);
        }
        sidx[i] = (scat_map == POS_GATHER) ? rc : (scat_map ? scat_map[rid] : rid);
    }
    __syncthreads();

    const int T0 = segs[0].K / BK;
    const int T1 = T0 + ((NSEG > 1) ? segs[1].K / BK : 0);
    const int T  = T1 + ((NSEG > 2) ? segs[2].K / BK : 0);
    const int ts = T * blockIdx.y / gridDim.y;
    const int te = T * (blockIdx.y + 1) / gridDim.y;

    const int ar_row  = (BM == 256) ? tid : (tid & (BM - 1));
    const int ar_half = (BM == 256) ? 0 : (tid >> 7);

    const float* abase[3];
    #pragma unroll
    for (int s = 0; s < NSEG; s++)
        abase[s] = segs[s].base + (size_t)ridx[s * BM + ar_row] * segs[s].K
                   + ar_half * 16;

    float4 af[4];

    auto map_tile = [&](int t, int& s, int& k0) {
        if (NSEG > 2 && t >= T1)      { s = 2; k0 = (t - T1) * BK; }
        else if (NSEG > 1 && t >= T0) { s = 1; k0 = (t - T0) * BK; }
        else                          { s = 0; k0 = t * BK; }
    };
    auto issueA = [&](int t) {
        int s, k0; map_tile(t, s, k0);
        const float* p = abase[s] + k0;
        #pragma unroll
        for (int q = 0; q < 4; q++) af[q] = *(const float4*)(p + q * 4);
    };
    auto storeA = [&](int t, int buf) {
        int s, k0; map_tile(t, s, k0);
        const int rl = segs[s].relu;
        float* dst = As + buf * (BK * ASTR);
        #pragma unroll
        for (int q = 0; q < 4; q++) {
            float4 v = af[q];
            if (rl) {
                v.x = fmaxf(v.x, 0.f); v.y = fmaxf(v.y, 0.f);
                v.z = fmaxf(v.z, 0.f); v.w = fmaxf(v.w, 0.f);
            }
            int kk = ar_half * 16 + q * 4;
            dst[(kk + 0) * ASTR + ar_row] = v.x;
            dst[(kk + 1) * ASTR + ar_row] = v.y;
            dst[(kk + 2) * ASTR + ar_row] = v.z;
            dst[(kk + 3) * ASTR + ar_row] = v.w;
        }
    };
    auto issueW = [&](int t, int buf) {
        int s, k0; map_tile(t, s, k0);
        const float* wp = segs[s].W + (size_t)k0 * BN;
        uint32_t sa = (uint32_t)__cvta_generic_to_shared(Wsm + buf * (BK * BN));
        #pragma unroll
        for (int ps = 0; ps < WPASS; ps++) {
            int i = tid * 4 + ps * 1024;
            cp16(sa + i * 4, wp + i);
        }
    };

    unsigned long long acc2[4][8];
    #pragma unroll
    for (int p = 0; p < 4; p++)
        #pragma unroll
        for (int j = 0; j < 8; j++) acc2[p][j] = 0ull;

    issueA(ts); storeA(ts, 0); issueW(ts, 0); cp_commit();
    if (ts + 1 < te) issueA(ts + 1);
    cp_wait0();
    __syncthreads();

    for (int t = ts; t < te; t++) {
        int buf = (t - ts) & 1;
        if (t + 1 < te) { issueW(t + 1, buf ^ 1); cp_commit(); storeA(t + 1, buf ^ 1); }
        if (t + 2 < te) issueA(t + 2);

        const float* as = As  + buf * (BK * ASTR);
        const float* ws = Wsm + buf * (BK * BN);
        #pragma unroll
        for (int k = 0; k < BK; k++) {
            ulonglong2 alo = *(const ulonglong2*)(as + k * ASTR + ty * 4);
            ulonglong2 ahi = *(const ulonglong2*)(as + k * ASTR + BM / 2 + ty * 4);
            float4 wlo = *(const float4*)(ws + k * BN + tx * 4);
            float4 whi = *(const float4*)(ws + k * BN + BN / 2 + tx * 4);
            unsigned long long ar[4] = {alo.x, alo.y, ahi.x, ahi.y};
            unsigned long long bd[8] = {
                pack2(wlo.x), pack2(wlo.y), pack2(wlo.z), pack2(wlo.w),
                pack2(whi.x), pack2(whi.y), pack2(whi.z), pack2(whi.w)};
            #pragma unroll
            for (int p = 0; p < 4; p++)
                #pragma unroll
                for (int j = 0; j < 8; j++)
                    ffma2(acc2[p][j], ar[p], bd[j]);
        }
        cp_wait0();
        __syncthreads();
    }

    float bv[8];
    if (OUT == 1) {
        #pragma unroll
        for (int j = 0; j < 4; j++) {
            bv[j]     = bias ? bias[tx * 4 + j] : 0.f;
            bv[4 + j] = bias ? bias[BN / 2 + tx * 4 + j] : 0.f;
        }
    }
    #pragma unroll
    for (int h = 0; h < 8; h++) {
        int hh = h & 3;
        int p  = ((h >> 2) << 1) | (hh >> 1);
        int c  = hh & 1;
        int rl = (h < 4) ? (ty * 4 + hh) : (BM / 2 + ty * 4 + hh);
        if (row0 + rl < M) {
            float* op = out + (size_t)sidx[rl] * BN;
            if (OUT == 2) {
                float v0 = sel2(acc2[p][0], c), v1 = sel2(acc2[p][1], c);
                float v2 = sel2(acc2[p][2], c), v3 = sel2(acc2[p][3], c);
                asm volatile("red.global.add.v4.f32 [%0], {%1,%2,%3,%4};"
                             :: "l"(op + tx * 4), "f"(v0), "f"(v1), "f"(v2), "f"(v3)
                             : "memory");
                float u0 = sel2(acc2[p][4], c), u1 = sel2(acc2[p][5], c);
                float u2 = sel2(acc2[p][6], c), u3 = sel2(acc2[p][7], c);
                asm volatile("red.global.add.v4.f32 [%0], {%1,%2,%3,%4};"
                             :: "l"(op + BN / 2 + tx * 4), "f"(u0), "f"(u1), "f"(u2), "f"(u3)
                             : "memory");
            } else {
                float4 o0, o1;
                o0.x = sel2(acc2[p][0], c) + bv[0];
                o0.y = sel2(acc2[p][1], c) + bv[1];
                o0.z = sel2(acc2[p][2], c) + bv[2];
                o0.w = sel2(acc2[p][3], c) + bv[3];
                o1.x = sel2(acc2[p][4], c) + bv[4];
                o1.y = sel2(acc2[p][5], c) + bv[5];
                o1.z = sel2(acc2[p][6], c) + bv[6];
                o1.w = sel2(acc2[p][7], c) + bv[7];
                if (relu_out) {
                    o0.x = fmaxf(o0.x, 0.f); o0.y = fmaxf(o0.y, 0.f);
                    o0.z = fmaxf(o0.z, 0.f); o0.w = fmaxf(o0.w, 0.f);
                    o1.x = fmaxf(o1.x, 0.f); o1.y = fmaxf(o1.y, 0.f);
                    o1.z = fmaxf(o1.z, 0.f); o1.w = fmaxf(o1.w, 0.f);
                }
                *(float4*)(op + tx * 4) = o0;
                *(float4*)(op + BN / 2 + tx * 4) = o1;
            }
        }
    }
}

// ---------------- layer-3 master kernels ----------------

__global__ __launch_bounds__(256) void master_node_kernel(
    const float* __restrict__ x2, const float* __restrict__ ws3,
    const float* __restrict__ bs3, float* __restrict__ out)
{
    int g = blockIdx.x;
    int c = threadIdx.x;
    const float* xr = x2 + (size_t)g * NODES_PER_GRAPH * 128;
    float acc = bs3[c];
    #pragma unroll 8
    for (int k = 0; k < 128; k++)
        acc += fmaxf(xr[k], 0.f) * ws3[(size_t)k * 256 + c];
    out[(size_t)g * 256 + c] = acc;
}

// out[g] += relu_x2[src]@wmx3 + e2@wme3 over list3 positions (warp per edge)
__global__ __launch_bounds__(256) void master_edge3_kernel(
    const float* __restrict__ x2,
    const int* __restrict__ src, const int* __restrict__ dst,
    const float* __restrict__ wmx3, const float* __restrict__ wme3,
    float* __restrict__ out)
{
    int cnt = d_cnt[2];
    int lane = threadIdx.x & 31;
    for (int i = blockIdx.x * 8 + (threadIdx.x >> 5); i < cnt; i += gridDim.x * 8) {
        int e  = d_list3[i];
        int sh = src[e];
        int g  = dst[e] / NODES_PER_GRAPH;
        float acc[8];
        #pragma unroll
        for (int j = 0; j < 8; j++) acc[j] = 0.f;
        const float* xr = x2 + (size_t)sh * 128;
        for (int k = 0; k < 128; k++) {
            float a = fmaxf(xr[k], 0.f);
            const float* wr = wmx3 + (size_t)k * 256;
            #pragma unroll
            for (int j = 0; j < 8; j++) acc[j] += a * wr[lane + j * 32];
        }
        const float* er = g_e2c + (size_t)i * 64;
        for (int k = 0; k < 64; k++) {
            float a = er[k];
            const float* wr = wme3 + (size_t)k * 256;
            #pragma unroll
            for (int j = 0; j < 8; j++) acc[j] += a * wr[lane + j * 32];
        }
        float* op = out + (size_t)g * 256;
        #pragma unroll
        for (int j = 0; j < 8; j++) atomicAdd(op + lane + j * 32, acc[j]);
    }
}

template<int BM, int BN, int BK, int NSEG>
static int smem_bytes() {
    constexpr int ASTR = BM + 4;
    return (2 * BK * ASTR + 2 * BK * BN) * 4 + NSEG * BM * 4 + BM * 4;
}

extern "C" void kernel_launch(void* const* d_in, const int* in_sizes, int n_in,
                              void* d_out, int out_size)
{
    const float* x         = (const float*)d_in[0];
    const int*   edge_idx  = (const int*)d_in[1];
    const float* edge_attr = (const float*)d_in[2];
    const float* w_proj    = (const float*)d_in[4];
    const float* b_proj    = (const float*)d_in[5];
    const float* P[30];
    for (int i = 0; i < 30 && i < n_in; i++) P[i] = (const float*)d_in[i];

    const int* src = edge_idx;
    const int* dst = edge_idx + N_EDGES;
    float* out = (float*)d_out;

    void* p;
    cudaGetSymbolAddress(&p, g_x1);     float* x1_p    = (float*)p;
    cudaGetSymbolAddress(&p, g_x2);     float* x2_p    = (float*)p;
    cudaGetSymbolAddress(&p, g_aggx);   float* aggx_p  = (float*)p;
    cudaGetSymbolAddress(&p, g_agga);   float* agga_p  = (float*)p;
    cudaGetSymbolAddress(&p, g_aggx2);  float* aggx2_p = (float*)p;
    cudaGetSymbolAddress(&p, g_agge1);  float* agge1_p = (float*)p;
    cudaGetSymbolAddress(&p, g_ec);     float* ec_p    = (float*)p;
    cudaGetSymbolAddress(&p, g_e1c);    float* e1c_p   = (float*)p;
    cudaGetSymbolAddress(&p, g_e2c);    float* e2c_p   = (float*)p;
    cudaGetSymbolAddress(&p, g_wpm);    float* wpm_p   = (float*)p;
    cudaGetSymbolAddress(&p, d_list2);  const int* l2  = (const int*)p;
    cudaGetSymbolAddress(&p, d_list3);  const int* l3  = (const int*)p;
    cudaGetSymbolAddress(&p, d_pos2);   const int* pos2 = (const int*)p;
    cudaGetSymbolAddress(&p, d_nlist1); const int* n1  = (const int*)p;
    cudaGetSymbolAddress(&p, d_nlist2); const int* n2  = (const int*)p;
    cudaGetSymbolAddress(&p, d_cnt);    const int* cnt = (const int*)p;
    const int* c_n2 = cnt + 0;
    const int* c_l2 = cnt + 1;
    const int* c_l3 = cnt + 2;
    const int* c_n1 = cnt + 3;

    static cudaStream_t sB = nullptr, sC = nullptr, sD = nullptr;
    static cudaEvent_t evRoot, evCW, evMark, evCSR, evL2, evN1, evSeed, evG1,
                       evS2, evE1, evX1, evE2;
    if (!sB) {
        cudaFuncSetAttribute(gemm_kernel<256, 64, 16, 1, 1>,
            cudaFuncAttributeMaxDynamicSharedMemorySize, smem_bytes<256, 64, 16, 1>());
        cudaFuncSetAttribute(gemm_kernel<256, 64, 16, 3, 2>,
            cudaFuncAttributeMaxDynamicSharedMemorySize, smem_bytes<256, 64, 16, 3>());
        cudaFuncSetAttribute(gemm_kernel<128, 128, 32, 1, 2>,
            cudaFuncAttributeMaxDynamicSharedMemorySize, smem_bytes<128, 128, 32, 1>());
        cudaFuncSetAttribute(gemm_kernel<128, 128, 32, 2, 2>,
            cudaFuncAttributeMaxDynamicSharedMemorySize, smem_bytes<128, 128, 32, 2>());
        cudaFuncSetAttribute(gemm_kernel<128, 128, 32, 3, 2>,
            cudaFuncAttributeMaxDynamicSharedMemorySize, smem_bytes<128, 128, 32, 3>());
        cudaStreamCreateWithFlags(&sB, cudaStreamNonBlocking);
        cudaStreamCreateWithFlags(&sC, cudaStreamNonBlocking);
        cudaStreamCreateWithFlags(&sD, cudaStreamNonBlocking);
        cudaEventCreateWithFlags(&evRoot, cudaEventDisableTiming);
        cudaEventCreateWithFlags(&evCW,   cudaEventDisableTiming);
        cudaEventCreateWithFlags(&evMark, cudaEventDisableTiming);
        cudaEventCreateWithFlags(&evCSR,  cudaEventDisableTiming);
        cudaEventCreateWithFlags(&evL2,   cudaEventDisableTiming);
        cudaEventCreateWithFlags(&evN1,   cudaEventDisableTiming);
        cudaEventCreateWithFlags(&evSeed, cudaEventDisableTiming);
        cudaEventCreateWithFlags(&evG1,   cudaEventDisableTiming);
        cudaEventCreateWithFlags(&evS2,   cudaEventDisableTiming);
        cudaEventCreateWithFlags(&evE1,   cudaEventDisableTiming);
        cudaEventCreateWithFlags(&evX1,   cudaEventDisableTiming);
        cudaEventCreateWithFlags(&evE2,   cudaEventDisableTiming);
    }

    Seg z = {nullptr, nullptr, nullptr, 0, 0};
    const int NGRID = (N_NODES + 255) / 256;

    // ---- fork root: stream C does combine_w concurrently with marking ----
    cudaEventRecord(evRoot, 0);
    cudaStreamWaitEvent(sC, evRoot, 0);
    combine_w_kernel<<<129, 128, 0, sC>>>(w_proj, b_proj, P[9]);   // P[9]=wme1
    cudaEventRecord(evCW, sC);

    // ---- chain A: marking (+ fused degree count) ----
    zero_kernel<<<256, 256>>>();
    mark2_count_scan<<<2048, 256>>>(src, dst);
    cudaEventRecord(evMark, 0);

    // ---- stream D: CSR build (single-pass scan + scatter) ----
    cudaStreamWaitEvent(sD, evMark, 0);
    scan_fused_kernel<<<SCAN_NB, SCAN_B, 0, sD>>>();
    scatter_csr_kernel<<<1024, 256, 0, sD>>>(dst);
    cudaEventRecord(evCSR, sD);

    // ---- stream C: seed2 (needs nlist2) ----
    cudaStreamWaitEvent(sC, evMark, 0);
    seed2_kernel<<<256, 256, 0, sC>>>(x2_p, P[15]);
    cudaEventRecord(evS2, sC);

    // ---- chain A: list2 + sorted nodes1 ----
    list2_scan<<<2048, 256>>>(src, dst);
    cudaEventRecord(evL2, 0);
    nodes1_kernel<<<NGRID, 256>>>();
    cudaEventRecord(evN1, 0);

    // ---- stream D: seed x1 then G1 = x@ws1 (red-add), overlaps agg1 ----
    cudaStreamWaitEvent(sD, evN1, 0);
    cudaStreamWaitEvent(sD, evCW, 0);
    seed_x1_kernel<<<512, 256, 0, sD>>>(x1_p, P[7]);
    cudaEventRecord(evSeed, sD);
    {
        Seg a = {x, nullptr, P[6], 256, 0};
        gemm_kernel<128, 128, 32, 1, 2>
            <<<dim3(CAP_N1 / 128, 1), 256, smem_bytes<128, 128, 32, 1>(), sD>>>(
            a, z, z, nullptr, 0, x1_p, n1, nullptr, c_n1);
    }
    cudaEventRecord(evG1, sD);

    // ---- chain B: e0 -> e1 (seed + split-K + relu) ----
    cudaStreamWaitEvent(sB, evL2, 0);
    {
        Seg a = {edge_attr, nullptr, w_proj, 128, 0};
        gemm_kernel<256, 64, 16, 1, 1>
            <<<CAP_L2 / 256, 256, smem_bytes<256, 64, 16, 1>(), sB>>>(
            a, z, z, b_proj, 0, ec_p, l2, POS_GATHER, c_l2);
    }
    seed_rows64_kernel<<<256, 256, 0, sB>>>(e1c_p, P[13], c_l2);
    {
        Seg a = {x,    src,        P[10], 256, 0};
        Seg b = {x,    dst,        P[11], 256, 0};
        Seg c = {ec_p, POS_GATHER, P[12], 64,  0};
        gemm_kernel<256, 64, 16, 3, 2>
            <<<dim3(CAP_L2 / 256, 2), 256, smem_bytes<256, 64, 16, 3>(), sB>>>(
            a, b, c, nullptr, 0, e1c_p, l2, POS_GATHER, c_l2);
    }
    relu_rows64_kernel<<<256, 256, 0, sB>>>(e1c_p, c_l2);
    cudaEventRecord(evE1, sB);
    seed_rows64_kernel<<<64, 256, 0, sB>>>(e2c_p, P[21], c_l3);

    // ---- chain A: CSR aggregation + G2 (x1 stays pre-relu in memory) ----
    cudaStreamWaitEvent(0, evCSR, 0);
    agg1_csr_kernel<<<2048, 256>>>(x, edge_attr, src);
    cudaStreamWaitEvent(0, evSeed, 0);
    {
        Seg a = {aggx_p, nullptr, P[8],  256, 0};
        Seg b = {agga_p, nullptr, wpm_p, 128, 0};
        gemm_kernel<128, 128, 32, 2, 2>
            <<<dim3(CAP_N1 / 128, 2), 256, smem_bytes<128, 128, 32, 2>()>>>(
            a, b, z, nullptr, 0, x1_p, n1, nullptr, c_n1);
    }
    cudaStreamWaitEvent(0, evG1, 0);
    cudaEventRecord(evX1, 0);                    // x1 final (pre-relu)

    // ---- chain B: e2 (relu(x1) on load; seed + split-K + relu) ----
    cudaStreamWaitEvent(sB, evX1, 0);
    {
        Seg a = {x1_p,  src,   P[18], 128, 1};
        Seg b = {x1_p,  dst,   P[19], 128, 1};
        Seg c = {e1c_p, pos2,  P[20], 64,  0};
        gemm_kernel<256, 64, 16, 3, 2>
            <<<dim3(CAP_L3 / 256, 4), 256, smem_bytes<256, 64, 16, 3>(), sB>>>(
            a, b, c, nullptr, 0, e2c_p, l3, POS_GATHER, c_l3);
    }
    relu_rows64_kernel<<<64, 256, 0, sB>>>(e2c_p, c_l3);
    cudaEventRecord(evE2, sB);

    // ---- chain A: layer 2 + masters ----
    cudaStreamWaitEvent(0, evE1, 0);
    cudaStreamWaitEvent(0, evS2, 0);
    agg2_kernel<<<512, 256>>>(x1_p, src, dst);   // relu applied inline
    {
        Seg a = {x1_p,    nullptr, P[14], 128, 1};
        Seg b = {aggx2_p, nullptr, P[16], 128, 0};
        Seg c = {agge1_p, nullptr, P[17], 64,  0};
        gemm_kernel<128, 128, 32, 3, 2>
            <<<dim3(CAP_N2 / 128, 4), 256, smem_bytes<128, 128, 32, 3>()>>>(
            a, b, c, nullptr, 0, x2_p, n2, nullptr, c_n2);
    }
    master_node_kernel<<<N_GRAPHS, 256>>>(x2_p, P[22], P[23], out);
    cudaStreamWaitEvent(0, evE2, 0);
    master_edge3_kernel<<<128, 256>>>(x2_p, src, dst, P[24], P[25], out);
}